// round 3
// baseline (speedup 1.0000x reference)
#include <cuda_runtime.h>

#define DIMX 1024
#define TOKENS 8192
#define INNER 1024
#define HEADS 16
#define HEAD_DIM 64
#define SEQ 2048
#define BATCH 4

// Scratch (static device allocations are allowed; cudaMalloc is not)
__device__ float g_xn[TOKENS * DIMX];        // 32 MB  LayerNorm output
__device__ float g_qkv[TOKENS * 3 * INNER];  // 96 MB  QKV projection
__device__ float g_att[TOKENS * INNER];      // 32 MB  attention output

// ---------------------------------------------------------------------------
// LayerNorm: one block per row of 1024, 256 threads, float4 per thread
// ---------------------------------------------------------------------------
__global__ void __launch_bounds__(256) ln_kernel(const float* __restrict__ x,
                                                 const float* __restrict__ g,
                                                 const float* __restrict__ b,
                                                 float* __restrict__ out) {
    int row = blockIdx.x;
    int t = threadIdx.x;
    const float4* xr = reinterpret_cast<const float4*>(x + (size_t)row * DIMX);
    float4 v = xr[t];
    float s = v.x + v.y + v.z + v.w;
    float s2 = v.x * v.x + v.y * v.y + v.z * v.z + v.w * v.w;
    #pragma unroll
    for (int o = 16; o; o >>= 1) {
        s  += __shfl_xor_sync(0xffffffffu, s,  o);
        s2 += __shfl_xor_sync(0xffffffffu, s2, o);
    }
    __shared__ float ws[8], ws2[8];
    int w = t >> 5, l = t & 31;
    if (l == 0) { ws[w] = s; ws2[w] = s2; }
    __syncthreads();
    float sum = 0.f, sum2 = 0.f;
    #pragma unroll
    for (int i = 0; i < 8; i++) { sum += ws[i]; sum2 += ws2[i]; }
    float mu = sum * (1.0f / DIMX);
    float var = sum2 * (1.0f / DIMX) - mu * mu;
    float rstd = rsqrtf(var + 1e-5f);

    float4 gv = reinterpret_cast<const float4*>(g)[t];
    float4 bv = reinterpret_cast<const float4*>(b)[t];
    float4 o;
    o.x = (v.x - mu) * rstd * gv.x + bv.x;
    o.y = (v.y - mu) * rstd * gv.y + bv.y;
    o.z = (v.z - mu) * rstd * gv.z + bv.z;
    o.w = (v.w - mu) * rstd * gv.w + bv.w;
    reinterpret_cast<float4*>(out + (size_t)row * DIMX)[t] = o;
}

// ---------------------------------------------------------------------------
// SGEMM: C[M,N] = A[M,K] @ B[K,N] + bias[N]
// 128x128 tile, BK=16, 256 threads, 8x8 register micro-tile
// M,K multiples of 128/16; N multiple of 128.
// ---------------------------------------------------------------------------
__global__ void __launch_bounds__(256) sgemm_bias(const float* __restrict__ A,
                                                  const float* __restrict__ B,
                                                  const float* __restrict__ bias,
                                                  float* __restrict__ C,
                                                  int M, int N, int K) {
    const int BM = 128, BN = 128, BK = 16;
    __shared__ float As[BK][BM];   // transposed: As[k][m]
    __shared__ float Bs[BK][BN];
    int bx = blockIdx.x, by = blockIdx.y;
    int tid = threadIdx.x;
    int tr = tid >> 4;   // 0..15
    int tc = tid & 15;   // 0..15
    const float* Ab = A + (size_t)(by * BM) * K;
    const float* Bb = B + (size_t)bx * BN;

    float acc[8][8];
    #pragma unroll
    for (int i = 0; i < 8; i++)
        #pragma unroll
        for (int j = 0; j < 8; j++) acc[i][j] = 0.f;

    for (int k0 = 0; k0 < K; k0 += BK) {
        #pragma unroll
        for (int i = 0; i < 2; i++) {
            int idx = tid + i * 256;
            int m = idx >> 2;             // 0..127
            int kk = (idx & 3) << 2;      // 0,4,8,12
            float4 v = *reinterpret_cast<const float4*>(Ab + (size_t)m * K + k0 + kk);
            As[kk + 0][m] = v.x; As[kk + 1][m] = v.y;
            As[kk + 2][m] = v.z; As[kk + 3][m] = v.w;
        }
        #pragma unroll
        for (int i = 0; i < 2; i++) {
            int idx = tid + i * 256;
            int kk = idx >> 5;            // 0..15
            int n = (idx & 31) << 2;      // 0..124
            *reinterpret_cast<float4*>(&Bs[kk][n]) =
                *reinterpret_cast<const float4*>(Bb + (size_t)(k0 + kk) * N + n);
        }
        __syncthreads();
        #pragma unroll
        for (int kk = 0; kk < BK; kk++) {
            float ra[8], rb[8];
            #pragma unroll
            for (int j = 0; j < 8; j++) ra[j] = As[kk][tr * 8 + j];
            #pragma unroll
            for (int j = 0; j < 8; j++) rb[j] = Bs[kk][tc * 8 + j];
            #pragma unroll
            for (int i = 0; i < 8; i++)
                #pragma unroll
                for (int j = 0; j < 8; j++)
                    acc[i][j] += ra[i] * rb[j];
        }
        __syncthreads();
    }

    #pragma unroll
    for (int i = 0; i < 8; i++) {
        int m = by * BM + tr * 8 + i;
        float* Cr = C + (size_t)m * N + bx * BN + tc * 8;
        const float* br = bias + bx * BN + tc * 8;
        #pragma unroll
        for (int j = 0; j < 8; j++) Cr[j] = acc[i][j] + br[j];
    }
}

// ---------------------------------------------------------------------------
// Flash-style attention. Block = (q-tile of 64, head, batch). 256 threads,
// 16x16 thread grid, 4x4 micro-tile. Online softmax, fp32.
// qkv layout: [b*SEQ + s][3072]: q @ h*64, k @ 1024+h*64, v @ 2048+h*64
// out layout: [b*SEQ + s][INNER] at h*64+d
// ---------------------------------------------------------------------------
__global__ void __launch_bounds__(256) attn_kernel(const float* __restrict__ qkv,
                                                   float* __restrict__ out) {
    __shared__ float Qt[64][64];   // [k][r], pre-scaled
    __shared__ float KP[64][64];   // Kt [k][c] during S; P [r][c] during PV
    __shared__ float Vs[64][64];   // [j][d]

    int qt = blockIdx.x;   // 0..31
    int h  = blockIdx.y;   // 0..15
    int b  = blockIdx.z;   // 0..3
    int tid = threadIdx.x;
    int tx = tid & 15, ty = tid >> 4;
    int r0 = ty * 4, c0 = tx * 4;
    const size_t base = (size_t)b * SEQ * 3072;
    const int q0 = qt * 64;
    const float scale = 0.125f;   // 1/sqrt(64)

    // Load Q tile transposed & scaled: Qt[k][r]
    {
        int r = tid >> 2;                // 0..63
        int k4 = (tid & 3) * 16;         // 0,16,32,48
        const float* qp = qkv + base + (size_t)(q0 + r) * 3072 + h * 64;
        #pragma unroll
        for (int i = 0; i < 4; i++) {
            float4 v = *reinterpret_cast<const float4*>(qp + k4 + i * 4);
            Qt[k4 + i * 4 + 0][r] = v.x * scale;
            Qt[k4 + i * 4 + 1][r] = v.y * scale;
            Qt[k4 + i * 4 + 2][r] = v.z * scale;
            Qt[k4 + i * 4 + 3][r] = v.w * scale;
        }
    }

    float m[4], l[4], O[4][4];
    #pragma unroll
    for (int i = 0; i < 4; i++) {
        m[i] = -1e30f; l[i] = 0.f;
        #pragma unroll
        for (int j = 0; j < 4; j++) O[i][j] = 0.f;
    }

    for (int kt = 0; kt < SEQ; kt += 64) {
        __syncthreads();   // previous tile's P/V fully consumed
        {
            int r = tid >> 2;
            int k4 = (tid & 3) * 16;
            const float* kp = qkv + base + (size_t)(kt + r) * 3072 + 1024 + h * 64;
            #pragma unroll
            for (int i = 0; i < 4; i++) {
                float4 v = *reinterpret_cast<const float4*>(kp + k4 + i * 4);
                KP[k4 + i * 4 + 0][r] = v.x;
                KP[k4 + i * 4 + 1][r] = v.y;
                KP[k4 + i * 4 + 2][r] = v.z;
                KP[k4 + i * 4 + 3][r] = v.w;
            }
            const float* vp = qkv + base + (size_t)(kt + r) * 3072 + 2048 + h * 64;
            #pragma unroll
            for (int i = 0; i < 4; i++)
                *reinterpret_cast<float4*>(&Vs[r][k4 + i * 4]) =
                    *reinterpret_cast<const float4*>(vp + k4 + i * 4);
        }
        __syncthreads();

        // S[r][c] = sum_k Qt[k][r] * Kt[k][c]
        float s[4][4];
        #pragma unroll
        for (int i = 0; i < 4; i++)
            #pragma unroll
            for (int j = 0; j < 4; j++) s[i][j] = 0.f;
        #pragma unroll 8
        for (int k = 0; k < 64; k++) {
            float4 qa = *reinterpret_cast<const float4*>(&Qt[k][r0]);
            float4 kb = *reinterpret_cast<const float4*>(&KP[k][c0]);
            float ra[4] = {qa.x, qa.y, qa.z, qa.w};
            float rb[4] = {kb.x, kb.y, kb.z, kb.w};
            #pragma unroll
            for (int i = 0; i < 4; i++)
                #pragma unroll
                for (int j = 0; j < 4; j++)
                    s[i][j] += ra[i] * rb[j];
        }

        // Online softmax: row state shared across the 16 tx lanes of each row
        float p[4][4], alpha[4];
        #pragma unroll
        for (int i = 0; i < 4; i++) {
            float mx = fmaxf(fmaxf(s[i][0], s[i][1]), fmaxf(s[i][2], s[i][3]));
            #pragma unroll
            for (int o = 1; o < 16; o <<= 1)
                mx = fmaxf(mx, __shfl_xor_sync(0xffffffffu, mx, o));
            float mn = fmaxf(m[i], mx);
            alpha[i] = __expf(m[i] - mn);
            m[i] = mn;
            float rs = 0.f;
            #pragma unroll
            for (int j = 0; j < 4; j++) {
                p[i][j] = __expf(s[i][j] - mn);
                rs += p[i][j];
            }
            #pragma unroll
            for (int o = 1; o < 16; o <<= 1)
                rs += __shfl_xor_sync(0xffffffffu, rs, o);
            l[i] = l[i] * alpha[i] + rs;
        }

        __syncthreads();   // all threads done reading KP as Kt

        // P[r][c] into KP (row-major); PV reads rows within own warp only
        #pragma unroll
        for (int i = 0; i < 4; i++)
            *reinterpret_cast<float4*>(&KP[r0 + i][c0]) =
                make_float4(p[i][0], p[i][1], p[i][2], p[i][3]);
        __syncwarp();

        #pragma unroll
        for (int i = 0; i < 4; i++)
            #pragma unroll
            for (int j = 0; j < 4; j++) O[i][j] *= alpha[i];

        #pragma unroll 4
        for (int j = 0; j < 64; j++) {
            float4 vv = *reinterpret_cast<const float4*>(&Vs[j][c0]);
            float rv[4] = {vv.x, vv.y, vv.z, vv.w};
            float pr[4];
            #pragma unroll
            for (int i = 0; i < 4; i++) pr[i] = KP[r0 + i][j];
            #pragma unroll
            for (int i = 0; i < 4; i++)
                #pragma unroll
                for (int jj = 0; jj < 4; jj++)
                    O[i][jj] += pr[i] * rv[jj];
        }
    }

    #pragma unroll
    for (int i = 0; i < 4; i++) {
        float inv = 1.f / l[i];
        float* op = out + (size_t)(b * SEQ + q0 + r0 + i) * INNER + h * 64 + c0;
        *reinterpret_cast<float4*>(op) =
            make_float4(O[i][0] * inv, O[i][1] * inv, O[i][2] * inv, O[i][3] * inv);
    }
}

// ---------------------------------------------------------------------------
extern "C" void kernel_launch(void* const* d_in, const int* in_sizes, int n_in,
                              void* d_out, int out_size) {
    const float* x     = (const float*)d_in[0];
    const float* ln_g  = (const float*)d_in[1];
    const float* ln_b  = (const float*)d_in[2];
    const float* w_qkv = (const float*)d_in[3];
    const float* b_qkv = (const float*)d_in[4];
    const float* w_out = (const float*)d_in[5];
    const float* b_out = (const float*)d_in[6];
    float* out = (float*)d_out;

    float *xn, *qkvb, *att;
    cudaGetSymbolAddress((void**)&xn,   g_xn);
    cudaGetSymbolAddress((void**)&qkvb, g_qkv);
    cudaGetSymbolAddress((void**)&att,  g_att);

    ln_kernel<<<TOKENS, 256>>>(x, ln_g, ln_b, xn);
    sgemm_bias<<<dim3(3 * INNER / 128, TOKENS / 128), 256>>>(
        xn, w_qkv, b_qkv, qkvb, TOKENS, 3 * INNER, DIMX);
    attn_kernel<<<dim3(SEQ / 64, HEADS, BATCH), 256>>>(qkvb, att);
    sgemm_bias<<<dim3(DIMX / 128, TOKENS / 128), 256>>>(
        att, w_out, b_out, out, TOKENS, DIMX, INNER);
}

// round 5
// speedup vs baseline: 1.3384x; 1.3384x over previous
#include <cuda_runtime.h>
#include <cuda_bf16.h>
#include <cstdint>

#define DIMX 1024
#define TOKENS 8192
#define INNER 1024
#define HEADS 16
#define HEAD_DIM 64
#define SEQ 2048
#define BATCH 4
#define GK 1024          // K of both GEMMs
#define KCHUNK 32        // bf16 K per pipeline stage
#define NCHUNK (GK / KCHUNK)   // 32

// ---------------------------------------------------------------------------
// Scratch (static device arrays; cudaMalloc forbidden)
// ---------------------------------------------------------------------------
__device__ __nv_bfloat16 g_xnh[TOKENS * DIMX];
__device__ __nv_bfloat16 g_xnl[TOKENS * DIMX];
__device__ __nv_bfloat16 g_wqh[3 * INNER * DIMX];   // w_qkv^T [3072][1024]
__device__ __nv_bfloat16 g_wql[3 * INNER * DIMX];
__device__ __nv_bfloat16 g_woh[DIMX * INNER];       // w_out^T [1024][1024]
__device__ __nv_bfloat16 g_wol[DIMX * INNER];
__device__ float         g_qkv[TOKENS * 3 * INNER]; // fp32 QKV (attn input)
__device__ __nv_bfloat16 g_ath[TOKENS * INNER];     // attention out hi/lo
__device__ __nv_bfloat16 g_atl[TOKENS * INNER];

// ---------------------------------------------------------------------------
// Base-ISA helpers only (no 'a'-suffix features: target is bare sm_103)
// ---------------------------------------------------------------------------
__device__ __forceinline__ uint32_t smem_u32(const void* p) {
    uint32_t a;
    asm("{ .reg .u64 t; cvta.to.shared.u64 t, %1; cvt.u32.u64 %0, t; }" : "=r"(a) : "l"(p));
    return a;
}
#define CP_ASYNC16(dst, src) \
    asm volatile("cp.async.cg.shared.global [%0], [%1], 16;" :: "r"(dst), "l"(src) : "memory")
#define CP_COMMIT() asm volatile("cp.async.commit_group;" ::: "memory")
#define CP_WAIT(n)  asm volatile("cp.async.wait_group %0;" :: "n"(n) : "memory")

__device__ __forceinline__ uint32_t lds_u32(uint32_t addr) {
    uint32_t v;
    asm volatile("ld.shared.b32 %0, [%1];" : "=r"(v) : "r"(addr));
    return v;
}

// mma.sync m16n8k16 row.col f32.bf16.bf16.f32 (base feature, sm_80+)
__device__ __forceinline__ void mma16816(float* c, const uint32_t* a, const uint32_t* b) {
    asm volatile(
        "mma.sync.aligned.m16n8k16.row.col.f32.bf16.bf16.f32 "
        "{%0,%1,%2,%3}, {%4,%5,%6,%7}, {%8,%9}, {%0,%1,%2,%3};"
        : "+f"(c[0]), "+f"(c[1]), "+f"(c[2]), "+f"(c[3])
        : "r"(a[0]), "r"(a[1]), "r"(a[2]), "r"(a[3]), "r"(b[0]), "r"(b[1]));
}

__device__ __forceinline__ void split_bf(float v, __nv_bfloat16& h, __nv_bfloat16& l) {
    h = __float2bfloat16_rn(v);
    l = __float2bfloat16_rn(v - __bfloat162float(h));
}

// ---------------------------------------------------------------------------
// LayerNorm -> bf16 hi/lo
// ---------------------------------------------------------------------------
__global__ void __launch_bounds__(256) ln_kernel(const float* __restrict__ x,
                                                 const float* __restrict__ g,
                                                 const float* __restrict__ b,
                                                 __nv_bfloat16* __restrict__ oh,
                                                 __nv_bfloat16* __restrict__ ol) {
    int row = blockIdx.x;
    int t = threadIdx.x;
    float4 v = reinterpret_cast<const float4*>(x + (size_t)row * DIMX)[t];
    float s = v.x + v.y + v.z + v.w;
    float s2 = v.x * v.x + v.y * v.y + v.z * v.z + v.w * v.w;
    #pragma unroll
    for (int o = 16; o; o >>= 1) {
        s  += __shfl_xor_sync(0xffffffffu, s,  o);
        s2 += __shfl_xor_sync(0xffffffffu, s2, o);
    }
    __shared__ float ws[8], ws2[8];
    int w = t >> 5, l = t & 31;
    if (l == 0) { ws[w] = s; ws2[w] = s2; }
    __syncthreads();
    float sum = 0.f, sum2 = 0.f;
    #pragma unroll
    for (int i = 0; i < 8; i++) { sum += ws[i]; sum2 += ws2[i]; }
    float mu = sum * (1.0f / DIMX);
    float var = sum2 * (1.0f / DIMX) - mu * mu;
    float rstd = rsqrtf(var + 1e-5f);

    float4 gv = reinterpret_cast<const float4*>(g)[t];
    float4 bv = reinterpret_cast<const float4*>(b)[t];
    float o0 = (v.x - mu) * rstd * gv.x + bv.x;
    float o1 = (v.y - mu) * rstd * gv.y + bv.y;
    float o2 = (v.z - mu) * rstd * gv.z + bv.z;
    float o3 = (v.w - mu) * rstd * gv.w + bv.w;
    __nv_bfloat16 h0, h1, h2, h3, l0, l1, l2, l3;
    split_bf(o0, h0, l0); split_bf(o1, h1, l1);
    split_bf(o2, h2, l2); split_bf(o3, h3, l3);
    size_t p = (size_t)row * DIMX + t * 4;
    __nv_bfloat162* ph = reinterpret_cast<__nv_bfloat162*>(oh + p);
    __nv_bfloat162* pl = reinterpret_cast<__nv_bfloat162*>(ol + p);
    ph[0] = __halves2bfloat162(h0, h1); ph[1] = __halves2bfloat162(h2, h3);
    pl[0] = __halves2bfloat162(l0, l1); pl[1] = __halves2bfloat162(l2, l3);
}

// ---------------------------------------------------------------------------
// Weight transpose + split:  W[K][N] fp32 -> T{hi,lo}[N][K] bf16
// ---------------------------------------------------------------------------
__global__ void __launch_bounds__(256) transpose_split(const float* __restrict__ W,
                                                       __nv_bfloat16* __restrict__ Th,
                                                       __nv_bfloat16* __restrict__ Tl,
                                                       int K, int N) {
    __shared__ float tile[32][33];
    int n0 = blockIdx.x * 32, k0 = blockIdx.y * 32;
    int tx = threadIdx.x, ty = threadIdx.y;          // (32, 8)
    #pragma unroll
    for (int j = 0; j < 4; j++)
        tile[ty + j * 8][tx] = W[(size_t)(k0 + ty + j * 8) * N + n0 + tx];
    __syncthreads();
    #pragma unroll
    for (int j = 0; j < 4; j++) {
        float v = tile[tx][ty + j * 8];
        __nv_bfloat16 h, l;
        split_bf(v, h, l);
        size_t p = (size_t)(n0 + ty + j * 8) * K + k0 + tx;
        Th[p] = h; Tl[p] = l;
    }
}

// ---------------------------------------------------------------------------
// mma.sync GEMM (bf16x3 split precision):
//   C[M][Ntot] = A[M][1024] @ B^T + bias    (A,B stored [rows][K] bf16 hi/lo)
// CTA 128x128, 8 warps (2x4), warp tile 64x32, BK=32, 3-stage cp.async.
// Smem row stride 80B (40 bf16) -> conflict-free fragment LDS.
// ---------------------------------------------------------------------------
#define ROWB 80                      // padded smem row stride (bytes) for 32 bf16
#define COMP_BYTES (128 * ROWB)      // 10240 per matrix component
#define STAGE_BYTES (4 * COMP_BYTES) // Ah, Al, Bh, Bl
#define GEMM_SMEM (3 * STAGE_BYTES)  // 122880

__global__ void __launch_bounds__(256, 1) gemm_mma(const __nv_bfloat16* __restrict__ Ahi,
                                                   const __nv_bfloat16* __restrict__ Alo,
                                                   const __nv_bfloat16* __restrict__ Bhi,
                                                   const __nv_bfloat16* __restrict__ Blo,
                                                   const float* __restrict__ bias,
                                                   float* __restrict__ C, int Ntot) {
    extern __shared__ char smem[];
    const uint32_t sbase = smem_u32(smem);

    int tid = threadIdx.x;
    int wid = tid >> 5, lane = tid & 31;
    int wm = wid >> 2;          // 0..1  (M dir, 64 rows each)
    int wn = wid & 3;           // 0..3  (N dir, 32 cols each)
    int grp = lane >> 2;        // 0..7
    int tig = lane & 3;         // 0..3

    const int m0 = blockIdx.y * 128;
    const int n0 = blockIdx.x * 128;

    const __nv_bfloat16* gA[2] = { Ahi + (size_t)m0 * GK, Alo + (size_t)m0 * GK };
    const __nv_bfloat16* gB[2] = { Bhi + (size_t)n0 * GK, Blo + (size_t)n0 * GK };

    // issue cp.async for chunk c into stage st
    auto load_chunk = [&](int c, int st) {
        uint32_t sa = sbase + st * STAGE_BYTES;
        #pragma unroll
        for (int i = 0; i < 2; i++) {
            int id = tid + i * 256;
            int r = id >> 2;          // 0..127
            int q = id & 3;           // 16B quarter of the 64B row
            uint32_t dst = sa + (uint32_t)(r * ROWB + q * 16);
            size_t gsrc = (size_t)r * GK + c * KCHUNK + q * 8;
            CP_ASYNC16(dst + 0 * COMP_BYTES, gA[0] + gsrc);
            CP_ASYNC16(dst + 1 * COMP_BYTES, gA[1] + gsrc);
            CP_ASYNC16(dst + 2 * COMP_BYTES, gB[0] + gsrc);
            CP_ASYNC16(dst + 3 * COMP_BYTES, gB[1] + gsrc);
        }
        CP_COMMIT();
    };

    load_chunk(0, 0);
    load_chunk(1, 1);
    load_chunk(2, 2);

    float acc[4][4][4];
    #pragma unroll
    for (int mi = 0; mi < 4; mi++)
        #pragma unroll
        for (int ni = 0; ni < 4; ni++)
            #pragma unroll
            for (int j = 0; j < 4; j++) acc[mi][ni][j] = 0.f;

    // per-thread base offsets inside a component (bytes)
    //   A frag rows: wm*64 + mi*16 + grp (+8);  cols: tig*4 (+16) (+32 per k16)
    //   B frag rows: wn*32 + ni*8 + grp;        cols: tig*4 (+16) (+32 per k16)
    const uint32_t aRow0 = (uint32_t)(wm * 64 + grp) * ROWB + (uint32_t)tig * 4;
    const uint32_t bRow0 = (uint32_t)(wn * 32 + grp) * ROWB + (uint32_t)tig * 4;

    for (int c = 0; c < NCHUNK; c++) {
        if (c < NCHUNK - 2)      CP_WAIT(2);
        else if (c == NCHUNK - 2) CP_WAIT(1);
        else                      CP_WAIT(0);
        __syncthreads();

        uint32_t sa = sbase + (c % 3) * STAGE_BYTES;
        uint32_t sAh = sa, sAl = sa + COMP_BYTES;
        uint32_t sBh = sa + 2 * COMP_BYTES, sBl = sa + 3 * COMP_BYTES;

        #pragma unroll
        for (int s = 0; s < 2; s++) {          // two k16 steps per chunk
            const uint32_t ko = (uint32_t)s * 32;
            uint32_t ah[4][4], al[4][4], bh[4][2], bl[4][2];
            #pragma unroll
            for (int mi = 0; mi < 4; mi++) {
                uint32_t ra = aRow0 + (uint32_t)mi * 16 * ROWB + ko;
                ah[mi][0] = lds_u32(sAh + ra);
                ah[mi][1] = lds_u32(sAh + ra + 8 * ROWB);
                ah[mi][2] = lds_u32(sAh + ra + 16);
                ah[mi][3] = lds_u32(sAh + ra + 8 * ROWB + 16);
                al[mi][0] = lds_u32(sAl + ra);
                al[mi][1] = lds_u32(sAl + ra + 8 * ROWB);
                al[mi][2] = lds_u32(sAl + ra + 16);
                al[mi][3] = lds_u32(sAl + ra + 8 * ROWB + 16);
            }
            #pragma unroll
            for (int ni = 0; ni < 4; ni++) {
                uint32_t rb = bRow0 + (uint32_t)ni * 8 * ROWB + ko;
                bh[ni][0] = lds_u32(sBh + rb);
                bh[ni][1] = lds_u32(sBh + rb + 16);
                bl[ni][0] = lds_u32(sBl + rb);
                bl[ni][1] = lds_u32(sBl + rb + 16);
            }
            #pragma unroll
            for (int mi = 0; mi < 4; mi++)
                #pragma unroll
                for (int ni = 0; ni < 4; ni++) {
                    mma16816(acc[mi][ni], ah[mi], bh[ni]);   // hi*hi
                    mma16816(acc[mi][ni], ah[mi], bl[ni]);   // hi*lo
                    mma16816(acc[mi][ni], al[mi], bh[ni]);   // lo*hi
                }
        }
        __syncthreads();
        if (c + 3 < NCHUNK) load_chunk(c + 3, c % 3);
    }

    // epilogue: acc[mi][ni] rows {grp, grp+8}, cols {tig*2, tig*2+1}
    #pragma unroll
    for (int mi = 0; mi < 4; mi++) {
        int row0 = m0 + wm * 64 + mi * 16 + grp;
        #pragma unroll
        for (int ni = 0; ni < 4; ni++) {
            int col = n0 + wn * 32 + ni * 8 + tig * 2;
            float bx = bias[col], by = bias[col + 1];
            float2* p0 = reinterpret_cast<float2*>(C + (size_t)row0 * Ntot + col);
            float2* p1 = reinterpret_cast<float2*>(C + (size_t)(row0 + 8) * Ntot + col);
            *p0 = make_float2(acc[mi][ni][0] + bx, acc[mi][ni][1] + by);
            *p1 = make_float2(acc[mi][ni][2] + bx, acc[mi][ni][3] + by);
        }
    }
}

// ---------------------------------------------------------------------------
// Flash attention (fp32 scalar, unchanged math) -> bf16 hi/lo output
// ---------------------------------------------------------------------------
__global__ void __launch_bounds__(256) attn_kernel(const float* __restrict__ qkv,
                                                   __nv_bfloat16* __restrict__ oh,
                                                   __nv_bfloat16* __restrict__ ol) {
    __shared__ float Qt[64][64];
    __shared__ float KP[64][64];
    __shared__ float Vs[64][64];

    int qt = blockIdx.x, h = blockIdx.y, b = blockIdx.z;
    int tid = threadIdx.x;
    int tx = tid & 15, ty = tid >> 4;
    int r0 = ty * 4, c0 = tx * 4;
    const size_t base = (size_t)b * SEQ * 3072;
    const int q0 = qt * 64;
    const float scale = 0.125f;

    {
        int r = tid >> 2;
        int k4 = (tid & 3) * 16;
        const float* qp = qkv + base + (size_t)(q0 + r) * 3072 + h * 64;
        #pragma unroll
        for (int i = 0; i < 4; i++) {
            float4 v = *reinterpret_cast<const float4*>(qp + k4 + i * 4);
            Qt[k4 + i * 4 + 0][r] = v.x * scale;
            Qt[k4 + i * 4 + 1][r] = v.y * scale;
            Qt[k4 + i * 4 + 2][r] = v.z * scale;
            Qt[k4 + i * 4 + 3][r] = v.w * scale;
        }
    }

    float m[4], l[4], O[4][4];
    #pragma unroll
    for (int i = 0; i < 4; i++) {
        m[i] = -1e30f; l[i] = 0.f;
        #pragma unroll
        for (int j = 0; j < 4; j++) O[i][j] = 0.f;
    }

    for (int kt = 0; kt < SEQ; kt += 64) {
        __syncthreads();
        {
            int r = tid >> 2;
            int k4 = (tid & 3) * 16;
            const float* kp = qkv + base + (size_t)(kt + r) * 3072 + 1024 + h * 64;
            #pragma unroll
            for (int i = 0; i < 4; i++) {
                float4 v = *reinterpret_cast<const float4*>(kp + k4 + i * 4);
                KP[k4 + i * 4 + 0][r] = v.x;
                KP[k4 + i * 4 + 1][r] = v.y;
                KP[k4 + i * 4 + 2][r] = v.z;
                KP[k4 + i * 4 + 3][r] = v.w;
            }
            const float* vp = qkv + base + (size_t)(kt + r) * 3072 + 2048 + h * 64;
            #pragma unroll
            for (int i = 0; i < 4; i++)
                *reinterpret_cast<float4*>(&Vs[r][k4 + i * 4]) =
                    *reinterpret_cast<const float4*>(vp + k4 + i * 4);
        }
        __syncthreads();

        float s[4][4];
        #pragma unroll
        for (int i = 0; i < 4; i++)
            #pragma unroll
            for (int j = 0; j < 4; j++) s[i][j] = 0.f;
        #pragma unroll 8
        for (int k = 0; k < 64; k++) {
            float4 qa = *reinterpret_cast<const float4*>(&Qt[k][r0]);
            float4 kb = *reinterpret_cast<const float4*>(&KP[k][c0]);
            float ra[4] = {qa.x, qa.y, qa.z, qa.w};
            float rb[4] = {kb.x, kb.y, kb.z, kb.w};
            #pragma unroll
            for (int i = 0; i < 4; i++)
                #pragma unroll
                for (int j = 0; j < 4; j++)
                    s[i][j] += ra[i] * rb[j];
        }

        float p[4][4], alpha[4];
        #pragma unroll
        for (int i = 0; i < 4; i++) {
            float mx = fmaxf(fmaxf(s[i][0], s[i][1]), fmaxf(s[i][2], s[i][3]));
            #pragma unroll
            for (int o = 1; o < 16; o <<= 1)
                mx = fmaxf(mx, __shfl_xor_sync(0xffffffffu, mx, o));
            float mn = fmaxf(m[i], mx);
            alpha[i] = __expf(m[i] - mn);
            m[i] = mn;
            float rs = 0.f;
            #pragma unroll
            for (int j = 0; j < 4; j++) {
                p[i][j] = __expf(s[i][j] - mn);
                rs += p[i][j];
            }
            #pragma unroll
            for (int o = 1; o < 16; o <<= 1)
                rs += __shfl_xor_sync(0xffffffffu, rs, o);
            l[i] = l[i] * alpha[i] + rs;
        }

        __syncthreads();

        #pragma unroll
        for (int i = 0; i < 4; i++)
            *reinterpret_cast<float4*>(&KP[r0 + i][c0]) =
                make_float4(p[i][0], p[i][1], p[i][2], p[i][3]);
        __syncwarp();

        #pragma unroll
        for (int i = 0; i < 4; i++)
            #pragma unroll
            for (int j = 0; j < 4; j++) O[i][j] *= alpha[i];

        #pragma unroll 4
        for (int j = 0; j < 64; j++) {
            float4 vv = *reinterpret_cast<const float4*>(&Vs[j][c0]);
            float rv[4] = {vv.x, vv.y, vv.z, vv.w};
            float pr[4];
            #pragma unroll
            for (int i = 0; i < 4; i++) pr[i] = KP[r0 + i][j];
            #pragma unroll
            for (int i = 0; i < 4; i++)
                #pragma unroll
                for (int jj = 0; jj < 4; jj++)
                    O[i][jj] += pr[i] * rv[jj];
        }
    }

    #pragma unroll
    for (int i = 0; i < 4; i++) {
        float inv = 1.f / l[i];
        float v0 = O[i][0] * inv, v1 = O[i][1] * inv;
        float v2 = O[i][2] * inv, v3 = O[i][3] * inv;
        __nv_bfloat16 h0, h1, h2, h3, l0, l1, l2, l3;
        split_bf(v0, h0, l0); split_bf(v1, h1, l1);
        split_bf(v2, h2, l2); split_bf(v3, h3, l3);
        size_t p = (size_t)(b * SEQ + q0 + r0 + i) * INNER + h * 64 + c0;
        __nv_bfloat162* ph = reinterpret_cast<__nv_bfloat162*>(oh + p);
        __nv_bfloat162* pl = reinterpret_cast<__nv_bfloat162*>(ol + p);
        ph[0] = __halves2bfloat162(h0, h1); ph[1] = __halves2bfloat162(h2, h3);
        pl[0] = __halves2bfloat162(l0, l1); pl[1] = __halves2bfloat162(l2, l3);
    }
}

// ---------------------------------------------------------------------------
extern "C" void kernel_launch(void* const* d_in, const int* in_sizes, int n_in,
                              void* d_out, int out_size) {
    const float* x     = (const float*)d_in[0];
    const float* ln_g  = (const float*)d_in[1];
    const float* ln_b  = (const float*)d_in[2];
    const float* w_qkv = (const float*)d_in[3];
    const float* b_qkv = (const float*)d_in[4];
    const float* w_out = (const float*)d_in[5];
    const float* b_out = (const float*)d_in[6];
    float* out = (float*)d_out;

    __nv_bfloat16 *xnh, *xnl, *wqh, *wql, *woh, *wol, *ath, *atl;
    float* qkvb;
    cudaGetSymbolAddress((void**)&xnh, g_xnh);
    cudaGetSymbolAddress((void**)&xnl, g_xnl);
    cudaGetSymbolAddress((void**)&wqh, g_wqh);
    cudaGetSymbolAddress((void**)&wql, g_wql);
    cudaGetSymbolAddress((void**)&woh, g_woh);
    cudaGetSymbolAddress((void**)&wol, g_wol);
    cudaGetSymbolAddress((void**)&ath, g_ath);
    cudaGetSymbolAddress((void**)&atl, g_atl);
    cudaGetSymbolAddress((void**)&qkvb, g_qkv);

    cudaFuncSetAttribute(gemm_mma, cudaFuncAttributeMaxDynamicSharedMemorySize,
                         GEMM_SMEM);

    ln_kernel<<<TOKENS, 256>>>(x, ln_g, ln_b, xnh, xnl);
    transpose_split<<<dim3(3 * INNER / 32, DIMX / 32), dim3(32, 8)>>>(
        w_qkv, wqh, wql, DIMX, 3 * INNER);
    transpose_split<<<dim3(DIMX / 32, INNER / 32), dim3(32, 8)>>>(
        w_out, woh, wol, INNER, DIMX);
    gemm_mma<<<dim3(3 * INNER / 128, TOKENS / 128), 256, GEMM_SMEM>>>(
        xnh, xnl, wqh, wql, b_qkv, qkvb, 3 * INNER);
    attn_kernel<<<dim3(SEQ / 64, HEADS, BATCH), 256>>>(qkvb, ath, atl);
    gemm_mma<<<dim3(DIMX / 128, TOKENS / 128), 256, GEMM_SMEM>>>(
        ath, atl, woh, wol, b_out, out, DIMX);
}

// round 9
// speedup vs baseline: 2.8281x; 2.1130x over previous
#include <cuda_runtime.h>
#include <cuda_bf16.h>
#include <cstdint>

#define DIMX 1024
#define TOKENS 8192
#define INNER 1024
#define HEADS 16
#define HEAD_DIM 64
#define SEQ 2048
#define BATCH 4
#define GK 1024
#define KCHUNK 32
#define NCHUNK (GK / KCHUNK)

// ---------------------------------------------------------------------------
// Scratch
// ---------------------------------------------------------------------------
__device__ __nv_bfloat16 g_xnh[TOKENS * DIMX];
__device__ __nv_bfloat16 g_xnl[TOKENS * DIMX];
__device__ __nv_bfloat16 g_wqh[3 * INNER * DIMX];
__device__ __nv_bfloat16 g_wql[3 * INNER * DIMX];
__device__ __nv_bfloat16 g_woh[DIMX * INNER];
__device__ __nv_bfloat16 g_wol[DIMX * INNER];
__device__ float         g_qkv[TOKENS * 3 * INNER];
__device__ __nv_bfloat16 g_ath[TOKENS * INNER];
__device__ __nv_bfloat16 g_atl[TOKENS * INNER];
// head-major split QKV for attention
__device__ __nv_bfloat16 g_qh[BATCH * HEADS * SEQ * HEAD_DIM];
__device__ __nv_bfloat16 g_ql[BATCH * HEADS * SEQ * HEAD_DIM];
__device__ __nv_bfloat16 g_kh[BATCH * HEADS * SEQ * HEAD_DIM];
__device__ __nv_bfloat16 g_kl[BATCH * HEADS * SEQ * HEAD_DIM];
__device__ __nv_bfloat16 g_vth[BATCH * HEADS * HEAD_DIM * SEQ];  // [bh][d][s]
__device__ __nv_bfloat16 g_vtl[BATCH * HEADS * HEAD_DIM * SEQ];

// ---------------------------------------------------------------------------
// Helpers (base ISA only — target is bare sm_103)
// ---------------------------------------------------------------------------
__device__ __forceinline__ uint32_t smem_u32(const void* p) {
    uint32_t a;
    asm("{ .reg .u64 t; cvta.to.shared.u64 t, %1; cvt.u32.u64 %0, t; }" : "=r"(a) : "l"(p));
    return a;
}
#define CP_ASYNC16(dst, src) \
    asm volatile("cp.async.cg.shared.global [%0], [%1], 16;" :: "r"(dst), "l"(src) : "memory")
#define CP_COMMIT() asm volatile("cp.async.commit_group;" ::: "memory")
#define CP_WAIT(n)  asm volatile("cp.async.wait_group %0;" :: "n"(n) : "memory")

__device__ __forceinline__ uint32_t lds_u32(uint32_t addr) {
    uint32_t v;
    asm volatile("ld.shared.b32 %0, [%1];" : "=r"(v) : "r"(addr));
    return v;
}
__device__ __forceinline__ void ldsm_x4(uint32_t* r, uint32_t addr) {
    asm volatile("ldmatrix.sync.aligned.m8n8.x4.shared.b16 {%0,%1,%2,%3}, [%4];"
                 : "=r"(r[0]), "=r"(r[1]), "=r"(r[2]), "=r"(r[3]) : "r"(addr));
}
__device__ __forceinline__ void mma16816(float* c, const uint32_t* a, const uint32_t* b) {
    asm volatile(
        "mma.sync.aligned.m16n8k16.row.col.f32.bf16.bf16.f32 "
        "{%0,%1,%2,%3}, {%4,%5,%6,%7}, {%8,%9}, {%0,%1,%2,%3};"
        : "+f"(c[0]), "+f"(c[1]), "+f"(c[2]), "+f"(c[3])
        : "r"(a[0]), "r"(a[1]), "r"(a[2]), "r"(a[3]), "r"(b[0]), "r"(b[1]));
}
__device__ __forceinline__ void split_bf(float v, __nv_bfloat16& h, __nv_bfloat16& l) {
    h = __float2bfloat16_rn(v);
    l = __float2bfloat16_rn(v - __bfloat162float(h));
}
// pack (a,b) into bf16x2 hi word + residual lo word; low half = a
__device__ __forceinline__ void split_pack(float a, float b, uint32_t& hi, uint32_t& lo) {
    __nv_bfloat16 ha = __float2bfloat16_rn(a), hb = __float2bfloat16_rn(b);
    __nv_bfloat162 hp = __halves2bfloat162(ha, hb);
    hi = *reinterpret_cast<uint32_t*>(&hp);
    __nv_bfloat162 lp = __halves2bfloat162(
        __float2bfloat16_rn(a - __bfloat162float(ha)),
        __float2bfloat16_rn(b - __bfloat162float(hb)));
    lo = *reinterpret_cast<uint32_t*>(&lp);
}
__device__ __forceinline__ void store_split2(__nv_bfloat16* ph, __nv_bfloat16* pl,
                                             float a, float b) {
    __nv_bfloat16 ha, la, hb, lb;
    split_bf(a, ha, la); split_bf(b, hb, lb);
    *reinterpret_cast<__nv_bfloat162*>(ph) = __halves2bfloat162(ha, hb);
    *reinterpret_cast<__nv_bfloat162*>(pl) = __halves2bfloat162(la, lb);
}

// ---------------------------------------------------------------------------
// LayerNorm -> bf16 hi/lo
// ---------------------------------------------------------------------------
__global__ void __launch_bounds__(256) ln_kernel(const float* __restrict__ x,
                                                 const float* __restrict__ g,
                                                 const float* __restrict__ b,
                                                 __nv_bfloat16* __restrict__ oh,
                                                 __nv_bfloat16* __restrict__ ol) {
    int row = blockIdx.x;
    int t = threadIdx.x;
    float4 v = reinterpret_cast<const float4*>(x + (size_t)row * DIMX)[t];
    float s = v.x + v.y + v.z + v.w;
    float s2 = v.x * v.x + v.y * v.y + v.z * v.z + v.w * v.w;
    #pragma unroll
    for (int o = 16; o; o >>= 1) {
        s  += __shfl_xor_sync(0xffffffffu, s,  o);
        s2 += __shfl_xor_sync(0xffffffffu, s2, o);
    }
    __shared__ float ws[8], ws2[8];
    int w = t >> 5, l = t & 31;
    if (l == 0) { ws[w] = s; ws2[w] = s2; }
    __syncthreads();
    float sum = 0.f, sum2 = 0.f;
    #pragma unroll
    for (int i = 0; i < 8; i++) { sum += ws[i]; sum2 += ws2[i]; }
    float mu = sum * (1.0f / DIMX);
    float var = sum2 * (1.0f / DIMX) - mu * mu;
    float rstd = rsqrtf(var + 1e-5f);

    float4 gv = reinterpret_cast<const float4*>(g)[t];
    float4 bv = reinterpret_cast<const float4*>(b)[t];
    float o0 = (v.x - mu) * rstd * gv.x + bv.x;
    float o1 = (v.y - mu) * rstd * gv.y + bv.y;
    float o2 = (v.z - mu) * rstd * gv.z + bv.z;
    float o3 = (v.w - mu) * rstd * gv.w + bv.w;
    size_t p = (size_t)row * DIMX + t * 4;
    store_split2(oh + p, ol + p, o0, o1);
    store_split2(oh + p + 2, ol + p + 2, o2, o3);
}

// ---------------------------------------------------------------------------
// Weight transpose + split
// ---------------------------------------------------------------------------
__global__ void __launch_bounds__(256) transpose_split(const float* __restrict__ W,
                                                       __nv_bfloat16* __restrict__ Th,
                                                       __nv_bfloat16* __restrict__ Tl,
                                                       int K, int N) {
    __shared__ float tile[32][33];
    int n0 = blockIdx.x * 32, k0 = blockIdx.y * 32;
    int tx = threadIdx.x, ty = threadIdx.y;
    #pragma unroll
    for (int j = 0; j < 4; j++)
        tile[ty + j * 8][tx] = W[(size_t)(k0 + ty + j * 8) * N + n0 + tx];
    __syncthreads();
    #pragma unroll
    for (int j = 0; j < 4; j++) {
        float v = tile[tx][ty + j * 8];
        __nv_bfloat16 h, l;
        split_bf(v, h, l);
        size_t p = (size_t)(n0 + ty + j * 8) * K + k0 + tx;
        Th[p] = h; Tl[p] = l;
    }
}

// ---------------------------------------------------------------------------
// mma.sync GEMM (unchanged from R5 — passing at tensor=49.5%)
// ---------------------------------------------------------------------------
#define ROWB 80
#define COMP_BYTES (128 * ROWB)
#define STAGE_BYTES (4 * COMP_BYTES)
#define GEMM_SMEM (3 * STAGE_BYTES)

__global__ void __launch_bounds__(256, 1) gemm_mma(const __nv_bfloat16* __restrict__ Ahi,
                                                   const __nv_bfloat16* __restrict__ Alo,
                                                   const __nv_bfloat16* __restrict__ Bhi,
                                                   const __nv_bfloat16* __restrict__ Blo,
                                                   const float* __restrict__ bias,
                                                   float* __restrict__ C, int Ntot) {
    extern __shared__ char smem[];
    const uint32_t sbase = smem_u32(smem);

    int tid = threadIdx.x;
    int wid = tid >> 5, lane = tid & 31;
    int wm = wid >> 2, wn = wid & 3;
    int grp = lane >> 2, tig = lane & 3;

    const int m0 = blockIdx.y * 128;
    const int n0 = blockIdx.x * 128;

    const __nv_bfloat16* gA[2] = { Ahi + (size_t)m0 * GK, Alo + (size_t)m0 * GK };
    const __nv_bfloat16* gB[2] = { Bhi + (size_t)n0 * GK, Blo + (size_t)n0 * GK };

    auto load_chunk = [&](int c, int st) {
        uint32_t sa = sbase + st * STAGE_BYTES;
        #pragma unroll
        for (int i = 0; i < 2; i++) {
            int id = tid + i * 256;
            int r = id >> 2;
            int q = id & 3;
            uint32_t dst = sa + (uint32_t)(r * ROWB + q * 16);
            size_t gsrc = (size_t)r * GK + c * KCHUNK + q * 8;
            CP_ASYNC16(dst + 0 * COMP_BYTES, gA[0] + gsrc);
            CP_ASYNC16(dst + 1 * COMP_BYTES, gA[1] + gsrc);
            CP_ASYNC16(dst + 2 * COMP_BYTES, gB[0] + gsrc);
            CP_ASYNC16(dst + 3 * COMP_BYTES, gB[1] + gsrc);
        }
        CP_COMMIT();
    };

    load_chunk(0, 0);
    load_chunk(1, 1);
    load_chunk(2, 2);

    float acc[4][4][4];
    #pragma unroll
    for (int mi = 0; mi < 4; mi++)
        #pragma unroll
        for (int ni = 0; ni < 4; ni++)
            #pragma unroll
            for (int j = 0; j < 4; j++) acc[mi][ni][j] = 0.f;

    const uint32_t aRow0 = (uint32_t)(wm * 64 + grp) * ROWB + (uint32_t)tig * 4;
    const uint32_t bRow0 = (uint32_t)(wn * 32 + grp) * ROWB + (uint32_t)tig * 4;

    for (int c = 0; c < NCHUNK; c++) {
        if (c < NCHUNK - 2)      CP_WAIT(2);
        else if (c == NCHUNK - 2) CP_WAIT(1);
        else                      CP_WAIT(0);
        __syncthreads();

        uint32_t sa = sbase + (c % 3) * STAGE_BYTES;
        uint32_t sAh = sa, sAl = sa + COMP_BYTES;
        uint32_t sBh = sa + 2 * COMP_BYTES, sBl = sa + 3 * COMP_BYTES;

        #pragma unroll
        for (int s = 0; s < 2; s++) {
            const uint32_t ko = (uint32_t)s * 32;
            uint32_t ah[4][4], al[4][4], bh[4][2], bl[4][2];
            #pragma unroll
            for (int mi = 0; mi < 4; mi++) {
                uint32_t ra = aRow0 + (uint32_t)mi * 16 * ROWB + ko;
                ah[mi][0] = lds_u32(sAh + ra);
                ah[mi][1] = lds_u32(sAh + ra + 8 * ROWB);
                ah[mi][2] = lds_u32(sAh + ra + 16);
                ah[mi][3] = lds_u32(sAh + ra + 8 * ROWB + 16);
                al[mi][0] = lds_u32(sAl + ra);
                al[mi][1] = lds_u32(sAl + ra + 8 * ROWB);
                al[mi][2] = lds_u32(sAl + ra + 16);
                al[mi][3] = lds_u32(sAl + ra + 8 * ROWB + 16);
            }
            #pragma unroll
            for (int ni = 0; ni < 4; ni++) {
                uint32_t rb = bRow0 + (uint32_t)ni * 8 * ROWB + ko;
                bh[ni][0] = lds_u32(sBh + rb);
                bh[ni][1] = lds_u32(sBh + rb + 16);
                bl[ni][0] = lds_u32(sBl + rb);
                bl[ni][1] = lds_u32(sBl + rb + 16);
            }
            #pragma unroll
            for (int mi = 0; mi < 4; mi++)
                #pragma unroll
                for (int ni = 0; ni < 4; ni++) {
                    mma16816(acc[mi][ni], ah[mi], bh[ni]);
                    mma16816(acc[mi][ni], ah[mi], bl[ni]);
                    mma16816(acc[mi][ni], al[mi], bh[ni]);
                }
        }
        __syncthreads();
        if (c + 3 < NCHUNK) load_chunk(c + 3, c % 3);
    }

    #pragma unroll
    for (int mi = 0; mi < 4; mi++) {
        int row0 = m0 + wm * 64 + mi * 16 + grp;
        #pragma unroll
        for (int ni = 0; ni < 4; ni++) {
            int col = n0 + wn * 32 + ni * 8 + tig * 2;
            float bx = bias[col], by = bias[col + 1];
            float2* p0 = reinterpret_cast<float2*>(C + (size_t)row0 * Ntot + col);
            float2* p1 = reinterpret_cast<float2*>(C + (size_t)(row0 + 8) * Ntot + col);
            *p0 = make_float2(acc[mi][ni][0] + bx, acc[mi][ni][1] + by);
            *p1 = make_float2(acc[mi][ni][2] + bx, acc[mi][ni][3] + by);
        }
    }
}

// ---------------------------------------------------------------------------
// Prepass: fp32 QKV -> head-major bf16 hi/lo; Q pre-scaled; V transposed
// ---------------------------------------------------------------------------
__global__ void __launch_bounds__(256) prep_qkv(const float* __restrict__ qkv,
                                                __nv_bfloat16* __restrict__ qh,
                                                __nv_bfloat16* __restrict__ ql,
                                                __nv_bfloat16* __restrict__ kh,
                                                __nv_bfloat16* __restrict__ kl,
                                                __nv_bfloat16* __restrict__ vth,
                                                __nv_bfloat16* __restrict__ vtl) {
    __shared__ float vs[64][65];
    int st = blockIdx.x, h = blockIdx.y, b = blockIdx.z;
    int bh = b * HEADS + h;
    int s0 = st * 64;
    int tid = threadIdx.x;

    #pragma unroll
    for (int i = 0; i < 4; i++) {
        int id = tid + i * 256;              // 0..1023
        int row = id >> 4, c4 = (id & 15) * 4;
        const float* src = qkv + (size_t)(b * SEQ + s0 + row) * 3072 + h * 64 + c4;
        size_t dst = ((size_t)bh * SEQ + s0 + row) * 64 + c4;
        float4 qv = *reinterpret_cast<const float4*>(src);
        store_split2(qh + dst,     ql + dst,     qv.x * 0.125f, qv.y * 0.125f);
        store_split2(qh + dst + 2, ql + dst + 2, qv.z * 0.125f, qv.w * 0.125f);
        float4 kv = *reinterpret_cast<const float4*>(src + 1024);
        store_split2(kh + dst,     kl + dst,     kv.x, kv.y);
        store_split2(kh + dst + 2, kl + dst + 2, kv.z, kv.w);
        float4 vv = *reinterpret_cast<const float4*>(src + 2048);
        vs[row][c4 + 0] = vv.x; vs[row][c4 + 1] = vv.y;
        vs[row][c4 + 2] = vv.z; vs[row][c4 + 3] = vv.w;
    }
    __syncthreads();
    #pragma unroll
    for (int i = 0; i < 4; i++) {
        int id = tid + i * 256;
        int d = id >> 4, s4 = (id & 15) * 4;
        size_t dst = ((size_t)bh * HEAD_DIM + d) * SEQ + s0 + s4;
        store_split2(vth + dst,     vtl + dst,     vs[s4][d],     vs[s4 + 1][d]);
        store_split2(vth + dst + 2, vtl + dst + 2, vs[s4 + 2][d], vs[s4 + 3][d]);
    }
}

// ---------------------------------------------------------------------------
// Flash attention via mma.sync (bf16x3 split precision)
// CTA: 128 q-rows x 1 head; 8 warps x 16 rows; KV tiles of 64, double-buffered.
// ---------------------------------------------------------------------------
#define QT 128
#define KT 64
#define RSTR 144                         // padded smem row stride (bytes)
#define SM_QBYTES (QT * RSTR)            // 18432 per component
#define SM_STAGE0 (2 * SM_QBYTES)        // 36864
#define TILE_B (KT * RSTR)               // 9216
#define STAGE_B (4 * TILE_B)             // 36864
#define ATTN_SMEM (SM_STAGE0 + 2 * STAGE_B)   // 110592

__global__ void __launch_bounds__(256, 1)
attn_mma(const __nv_bfloat16* __restrict__ qh, const __nv_bfloat16* __restrict__ ql,
         const __nv_bfloat16* __restrict__ kh, const __nv_bfloat16* __restrict__ kl,
         const __nv_bfloat16* __restrict__ vth, const __nv_bfloat16* __restrict__ vtl,
         __nv_bfloat16* __restrict__ oh, __nv_bfloat16* __restrict__ ol) {
    extern __shared__ char smem[];
    const uint32_t sb = smem_u32(smem);
    const int tid = threadIdx.x;
    const int w = tid >> 5, lane = tid & 31;
    const int grp = lane >> 2, tig = lane & 3;
    const int qt = blockIdx.x, h = blockIdx.y, b = blockIdx.z;
    const int bh = b * HEADS + h;
    const int q0 = qt * QT;

    const __nv_bfloat16* qsrc[2] = { qh + ((size_t)bh * SEQ + q0) * 64,
                                     ql + ((size_t)bh * SEQ + q0) * 64 };
    const __nv_bfloat16* ksrc[2] = { kh + (size_t)bh * SEQ * 64,
                                     kl + (size_t)bh * SEQ * 64 };
    const __nv_bfloat16* vsrc[2] = { vth + (size_t)bh * HEAD_DIM * SEQ,
                                     vtl + (size_t)bh * HEAD_DIM * SEQ };

    // Q tile (hi/lo) -> smem
    #pragma unroll
    for (int i = 0; i < 8; i++) {
        int id = tid + i * 256;              // 0..2047
        int comp = id >> 10, rem = id & 1023;
        int row = rem >> 3, qq = rem & 7;
        CP_ASYNC16(sb + comp * SM_QBYTES + row * RSTR + qq * 16,
                   qsrc[comp] + (size_t)row * 64 + qq * 8);
    }
    CP_COMMIT();

    auto load_kv = [&](int kt_, int stg) {
        uint32_t sa = sb + SM_STAGE0 + stg * STAGE_B;
        #pragma unroll
        for (int i = 0; i < 8; i++) {
            int id = tid + i * 256;          // 0..2047
            int arr = id >> 9, rem = id & 511;
            int row = rem >> 3, qq = rem & 7;
            uint32_t dst = sa + arr * TILE_B + row * RSTR + qq * 16;
            const __nv_bfloat16* src;
            if (arr == 0)      src = ksrc[0] + (size_t)(kt_ + row) * 64 + qq * 8;
            else if (arr == 1) src = ksrc[1] + (size_t)(kt_ + row) * 64 + qq * 8;
            else if (arr == 2) src = vsrc[0] + (size_t)row * SEQ + kt_ + qq * 8;
            else               src = vsrc[1] + (size_t)row * SEQ + kt_ + qq * 8;
            CP_ASYNC16(dst, src);
        }
        CP_COMMIT();
    };

    load_kv(0, 0);
    load_kv(KT, 1);

    CP_WAIT(2);                 // Q group done
    __syncthreads();

    // Q fragments (loop-invariant)
    uint32_t qfh[4][4], qfl[4][4];
    {
        int arow = w * 16 + ((lane >> 3) & 1) * 8 + (lane & 7);
        int acol = (lane >> 4) * 16;
        #pragma unroll
        for (int j = 0; j < 4; j++) {
            ldsm_x4(qfh[j], sb + arow * RSTR + j * 32 + acol);
            ldsm_x4(qfl[j], sb + SM_QBYTES + arow * RSTR + j * 32 + acol);
        }
    }

    float m0 = -1e30f, m1 = -1e30f, l0 = 0.f, l1 = 0.f;
    float oacc[8][4];
    #pragma unroll
    for (int ni = 0; ni < 8; ni++)
        #pragma unroll
        for (int j = 0; j < 4; j++) oacc[ni][j] = 0.f;

    const int brow = (lane >> 4) * 8 + (lane & 7);
    const int bcol = ((lane >> 3) & 1) * 16;

    for (int c = 0; c < SEQ / KT; c++) {
        if (c < SEQ / KT - 1) CP_WAIT(1); else CP_WAIT(0);
        __syncthreads();
        uint32_t sa = sb + SM_STAGE0 + (c & 1) * STAGE_B;
        uint32_t sKh = sa, sKl = sa + TILE_B;
        uint32_t sVh = sa + 2 * TILE_B, sVl = sa + 3 * TILE_B;

        // S = Q K^T  (3 combos)
        float sacc[8][4];
        #pragma unroll
        for (int ni = 0; ni < 8; ni++)
            #pragma unroll
            for (int j = 0; j < 4; j++) sacc[ni][j] = 0.f;

        #pragma unroll
        for (int j = 0; j < 4; j++) {
            #pragma unroll
            for (int g = 0; g < 4; g++) {
                uint32_t kb[4], kb2[4];
                ldsm_x4(kb, sKh + (uint32_t)(g * 16 + brow) * RSTR + j * 32 + bcol);
                mma16816(sacc[2 * g],     qfh[j], kb);
                mma16816(sacc[2 * g + 1], qfh[j], kb + 2);
                mma16816(sacc[2 * g],     qfl[j], kb);
                mma16816(sacc[2 * g + 1], qfl[j], kb + 2);
                ldsm_x4(kb2, sKl + (uint32_t)(g * 16 + brow) * RSTR + j * 32 + bcol);
                mma16816(sacc[2 * g],     qfh[j], kb2);
                mma16816(sacc[2 * g + 1], qfh[j], kb2 + 2);
            }
        }

        // online softmax (rows grp / grp+8; quad reduction over tig lanes)
        float mx0 = -1e30f, mx1 = -1e30f;
        #pragma unroll
        for (int ni = 0; ni < 8; ni++) {
            mx0 = fmaxf(mx0, fmaxf(sacc[ni][0], sacc[ni][1]));
            mx1 = fmaxf(mx1, fmaxf(sacc[ni][2], sacc[ni][3]));
        }
        mx0 = fmaxf(mx0, __shfl_xor_sync(0xffffffffu, mx0, 1));
        mx0 = fmaxf(mx0, __shfl_xor_sync(0xffffffffu, mx0, 2));
        mx1 = fmaxf(mx1, __shfl_xor_sync(0xffffffffu, mx1, 1));
        mx1 = fmaxf(mx1, __shfl_xor_sync(0xffffffffu, mx1, 2));
        float mn0 = fmaxf(m0, mx0), mn1 = fmaxf(m1, mx1);
        float al0 = __expf(m0 - mn0), al1 = __expf(m1 - mn1);
        m0 = mn0; m1 = mn1;
        float rs0 = 0.f, rs1 = 0.f;
        #pragma unroll
        for (int ni = 0; ni < 8; ni++) {
            sacc[ni][0] = __expf(sacc[ni][0] - mn0);
            sacc[ni][1] = __expf(sacc[ni][1] - mn0);
            sacc[ni][2] = __expf(sacc[ni][2] - mn1);
            sacc[ni][3] = __expf(sacc[ni][3] - mn1);
            rs0 += sacc[ni][0] + sacc[ni][1];
            rs1 += sacc[ni][2] + sacc[ni][3];
        }
        rs0 += __shfl_xor_sync(0xffffffffu, rs0, 1);
        rs0 += __shfl_xor_sync(0xffffffffu, rs0, 2);
        rs1 += __shfl_xor_sync(0xffffffffu, rs1, 1);
        rs1 += __shfl_xor_sync(0xffffffffu, rs1, 2);
        l0 = l0 * al0 + rs0;
        l1 = l1 * al1 + rs1;

        #pragma unroll
        for (int ni = 0; ni < 8; ni++) {
            oacc[ni][0] *= al0; oacc[ni][1] *= al0;
            oacc[ni][2] *= al1; oacc[ni][3] *= al1;
        }

        // O += P V   (P fragments straight from registers; 3 combos)
        #pragma unroll
        for (int j = 0; j < 4; j++) {
            uint32_t phf[4], plf[4];
            split_pack(sacc[2 * j][0],     sacc[2 * j][1],     phf[0], plf[0]);
            split_pack(sacc[2 * j][2],     sacc[2 * j][3],     phf[1], plf[1]);
            split_pack(sacc[2 * j + 1][0], sacc[2 * j + 1][1], phf[2], plf[2]);
            split_pack(sacc[2 * j + 1][2], sacc[2 * j + 1][3], phf[3], plf[3]);
            #pragma unroll
            for (int g = 0; g < 4; g++) {
                uint32_t vb[4], vb2[4];
                ldsm_x4(vb, sVh + (uint32_t)(g * 16 + brow) * RSTR + j * 32 + bcol);
                mma16816(oacc[2 * g],     phf, vb);
                mma16816(oacc[2 * g + 1], phf, vb + 2);
                mma16816(oacc[2 * g],     plf, vb);
                mma16816(oacc[2 * g + 1], plf, vb + 2);
                ldsm_x4(vb2, sVl + (uint32_t)(g * 16 + brow) * RSTR + j * 32 + bcol);
                mma16816(oacc[2 * g],     phf, vb2);
                mma16816(oacc[2 * g + 1], phf, vb2 + 2);
            }
        }

        __syncthreads();
        if (c + 2 < SEQ / KT) load_kv((c + 2) * KT, c & 1);
    }

    // epilogue
    float inv0 = 1.f / l0, inv1 = 1.f / l1;
    int row0 = q0 + w * 16 + grp;
    size_t ob0 = ((size_t)(b * SEQ) + row0) * INNER + h * 64;
    size_t ob1 = ob0 + 8 * INNER;
    #pragma unroll
    for (int ni = 0; ni < 8; ni++) {
        int col = ni * 8 + tig * 2;
        store_split2(oh + ob0 + col, ol + ob0 + col,
                     oacc[ni][0] * inv0, oacc[ni][1] * inv0);
        store_split2(oh + ob1 + col, ol + ob1 + col,
                     oacc[ni][2] * inv1, oacc[ni][3] * inv1);
    }
}

// ---------------------------------------------------------------------------
extern "C" void kernel_launch(void* const* d_in, const int* in_sizes, int n_in,
                              void* d_out, int out_size) {
    const float* x     = (const float*)d_in[0];
    const float* ln_g  = (const float*)d_in[1];
    const float* ln_b  = (const float*)d_in[2];
    const float* w_qkv = (const float*)d_in[3];
    const float* b_qkv = (const float*)d_in[4];
    const float* w_out = (const float*)d_in[5];
    const float* b_out = (const float*)d_in[6];
    float* out = (float*)d_out;

    __nv_bfloat16 *xnh, *xnl, *wqh, *wql, *woh, *wol, *ath, *atl;
    __nv_bfloat16 *qh, *ql, *kh, *kl, *vth, *vtl;
    float* qkvb;
    cudaGetSymbolAddress((void**)&xnh, g_xnh);
    cudaGetSymbolAddress((void**)&xnl, g_xnl);
    cudaGetSymbolAddress((void**)&wqh, g_wqh);
    cudaGetSymbolAddress((void**)&wql, g_wql);
    cudaGetSymbolAddress((void**)&woh, g_woh);
    cudaGetSymbolAddress((void**)&wol, g_wol);
    cudaGetSymbolAddress((void**)&ath, g_ath);
    cudaGetSymbolAddress((void**)&atl, g_atl);
    cudaGetSymbolAddress((void**)&qkvb, g_qkv);
    cudaGetSymbolAddress((void**)&qh,  g_qh);
    cudaGetSymbolAddress((void**)&ql,  g_ql);
    cudaGetSymbolAddress((void**)&kh,  g_kh);
    cudaGetSymbolAddress((void**)&kl,  g_kl);
    cudaGetSymbolAddress((void**)&vth, g_vth);
    cudaGetSymbolAddress((void**)&vtl, g_vtl);

    cudaFuncSetAttribute(gemm_mma, cudaFuncAttributeMaxDynamicSharedMemorySize,
                         GEMM_SMEM);
    cudaFuncSetAttribute(attn_mma, cudaFuncAttributeMaxDynamicSharedMemorySize,
                         ATTN_SMEM);

    ln_kernel<<<TOKENS, 256>>>(x, ln_g, ln_b, xnh, xnl);
    transpose_split<<<dim3(3 * INNER / 32, DIMX / 32), dim3(32, 8)>>>(
        w_qkv, wqh, wql, DIMX, 3 * INNER);
    transpose_split<<<dim3(DIMX / 32, INNER / 32), dim3(32, 8)>>>(
        w_out, woh, wol, INNER, DIMX);
    gemm_mma<<<dim3(3 * INNER / 128, TOKENS / 128), 256, GEMM_SMEM>>>(
        xnh, xnl, wqh, wql, b_qkv, qkvb, 3 * INNER);
    prep_qkv<<<dim3(SEQ / 64, HEADS, BATCH), 256>>>(
        qkvb, qh, ql, kh, kl, vth, vtl);
    attn_mma<<<dim3(SEQ / QT, HEADS, BATCH), 256, ATTN_SMEM>>>(
        qh, ql, kh, kl, vth, vtl, ath, atl);
    gemm_mma<<<dim3(DIMX / 128, TOKENS / 128), 256, GEMM_SMEM>>>(
        ath, atl, woh, wol, b_out, out, DIMX);
}

// round 12
// speedup vs baseline: 2.8289x; 1.0003x over previous
#include <cuda_runtime.h>
#include <cuda_bf16.h>
#include <cstdint>

#define DIMX 1024
#define TOKENS 8192
#define INNER 1024
#define HEADS 16
#define HEAD_DIM 64
#define SEQ 2048
#define BATCH 4
#define GK 1024
#define KCHUNK 32
#define NCHUNK (GK / KCHUNK)

// ---------------------------------------------------------------------------
// Scratch
// ---------------------------------------------------------------------------
__device__ __nv_bfloat16 g_xnh[TOKENS * DIMX];
__device__ __nv_bfloat16 g_xnl[TOKENS * DIMX];
__device__ __nv_bfloat16 g_wqh[3 * INNER * DIMX];
__device__ __nv_bfloat16 g_wql[3 * INNER * DIMX];
__device__ __nv_bfloat16 g_woh[DIMX * INNER];
__device__ __nv_bfloat16 g_wol[DIMX * INNER];
__device__ float         g_qkv[TOKENS * 3 * INNER];
__device__ __nv_bfloat16 g_ath[TOKENS * INNER];
__device__ __nv_bfloat16 g_atl[TOKENS * INNER];
// head-major split QKV for attention
__device__ __nv_bfloat16 g_qh[BATCH * HEADS * SEQ * HEAD_DIM];
__device__ __nv_bfloat16 g_ql[BATCH * HEADS * SEQ * HEAD_DIM];
__device__ __nv_bfloat16 g_kh[BATCH * HEADS * SEQ * HEAD_DIM];
__device__ __nv_bfloat16 g_kl[BATCH * HEADS * SEQ * HEAD_DIM];
__device__ __nv_bfloat16 g_vth[BATCH * HEADS * HEAD_DIM * SEQ];  // [bh][d][s]
__device__ __nv_bfloat16 g_vtl[BATCH * HEADS * HEAD_DIM * SEQ];

// ---------------------------------------------------------------------------
// Helpers (base ISA only — target is bare sm_103)
// ---------------------------------------------------------------------------
__device__ __forceinline__ uint32_t smem_u32(const void* p) {
    uint32_t a;
    asm("{ .reg .u64 t; cvta.to.shared.u64 t, %1; cvt.u32.u64 %0, t; }" : "=r"(a) : "l"(p));
    return a;
}
#define CP_ASYNC16(dst, src) \
    asm volatile("cp.async.cg.shared.global [%0], [%1], 16;" :: "r"(dst), "l"(src) : "memory")
#define CP_COMMIT() asm volatile("cp.async.commit_group;" ::: "memory")
#define CP_WAIT(n)  asm volatile("cp.async.wait_group %0;" :: "n"(n) : "memory")

__device__ __forceinline__ void ldsm_x4(uint32_t* r, uint32_t addr) {
    asm volatile("ldmatrix.sync.aligned.m8n8.x4.shared.b16 {%0,%1,%2,%3}, [%4];"
                 : "=r"(r[0]), "=r"(r[1]), "=r"(r[2]), "=r"(r[3]) : "r"(addr));
}
__device__ __forceinline__ void mma16816(float* c, const uint32_t* a, const uint32_t* b) {
    asm volatile(
        "mma.sync.aligned.m16n8k16.row.col.f32.bf16.bf16.f32 "
        "{%0,%1,%2,%3}, {%4,%5,%6,%7}, {%8,%9}, {%0,%1,%2,%3};"
        : "+f"(c[0]), "+f"(c[1]), "+f"(c[2]), "+f"(c[3])
        : "r"(a[0]), "r"(a[1]), "r"(a[2]), "r"(a[3]), "r"(b[0]), "r"(b[1]));
}
__device__ __forceinline__ void split_bf(float v, __nv_bfloat16& h, __nv_bfloat16& l) {
    h = __float2bfloat16_rn(v);
    l = __float2bfloat16_rn(v - __bfloat162float(h));
}
// pack (a,b) into bf16x2 hi word + residual lo word; low half = a
__device__ __forceinline__ void split_pack(float a, float b, uint32_t& hi, uint32_t& lo) {
    __nv_bfloat16 ha = __float2bfloat16_rn(a), hb = __float2bfloat16_rn(b);
    __nv_bfloat162 hp = __halves2bfloat162(ha, hb);
    hi = *reinterpret_cast<uint32_t*>(&hp);
    __nv_bfloat162 lp = __halves2bfloat162(
        __float2bfloat16_rn(a - __bfloat162float(ha)),
        __float2bfloat16_rn(b - __bfloat162float(hb)));
    lo = *reinterpret_cast<uint32_t*>(&lp);
}
__device__ __forceinline__ void store_split2(__nv_bfloat16* ph, __nv_bfloat16* pl,
                                             float a, float b) {
    __nv_bfloat16 ha, la, hb, lb;
    split_bf(a, ha, la); split_bf(b, hb, lb);
    *reinterpret_cast<__nv_bfloat162*>(ph) = __halves2bfloat162(ha, hb);
    *reinterpret_cast<__nv_bfloat162*>(pl) = __halves2bfloat162(la, lb);
}

// ---------------------------------------------------------------------------
// LayerNorm -> bf16 hi/lo
// ---------------------------------------------------------------------------
__global__ void __launch_bounds__(256) ln_kernel(const float* __restrict__ x,
                                                 const float* __restrict__ g,
                                                 const float* __restrict__ b,
                                                 __nv_bfloat16* __restrict__ oh,
                                                 __nv_bfloat16* __restrict__ ol) {
    int row = blockIdx.x;
    int t = threadIdx.x;
    float4 v = reinterpret_cast<const float4*>(x + (size_t)row * DIMX)[t];
    float s = v.x + v.y + v.z + v.w;
    float s2 = v.x * v.x + v.y * v.y + v.z * v.z + v.w * v.w;
    #pragma unroll
    for (int o = 16; o; o >>= 1) {
        s  += __shfl_xor_sync(0xffffffffu, s,  o);
        s2 += __shfl_xor_sync(0xffffffffu, s2, o);
    }
    __shared__ float ws[8], ws2[8];
    int w = t >> 5, l = t & 31;
    if (l == 0) { ws[w] = s; ws2[w] = s2; }
    __syncthreads();
    float sum = 0.f, sum2 = 0.f;
    #pragma unroll
    for (int i = 0; i < 8; i++) { sum += ws[i]; sum2 += ws2[i]; }
    float mu = sum * (1.0f / DIMX);
    float var = sum2 * (1.0f / DIMX) - mu * mu;
    float rstd = rsqrtf(var + 1e-5f);

    float4 gv = reinterpret_cast<const float4*>(g)[t];
    float4 bv = reinterpret_cast<const float4*>(b)[t];
    float o0 = (v.x - mu) * rstd * gv.x + bv.x;
    float o1 = (v.y - mu) * rstd * gv.y + bv.y;
    float o2 = (v.z - mu) * rstd * gv.z + bv.z;
    float o3 = (v.w - mu) * rstd * gv.w + bv.w;
    size_t p = (size_t)row * DIMX + t * 4;
    store_split2(oh + p, ol + p, o0, o1);
    store_split2(oh + p + 2, ol + p + 2, o2, o3);
}

// ---------------------------------------------------------------------------
// Weight transpose + split
// ---------------------------------------------------------------------------
__global__ void __launch_bounds__(256) transpose_split(const float* __restrict__ W,
                                                       __nv_bfloat16* __restrict__ Th,
                                                       __nv_bfloat16* __restrict__ Tl,
                                                       int K, int N) {
    __shared__ float tile[32][33];
    int n0 = blockIdx.x * 32, k0 = blockIdx.y * 32;
    int tx = threadIdx.x, ty = threadIdx.y;
    #pragma unroll
    for (int j = 0; j < 4; j++)
        tile[ty + j * 8][tx] = W[(size_t)(k0 + ty + j * 8) * N + n0 + tx];
    __syncthreads();
    #pragma unroll
    for (int j = 0; j < 4; j++) {
        float v = tile[tx][ty + j * 8];
        __nv_bfloat16 h, l;
        split_bf(v, h, l);
        size_t p = (size_t)(n0 + ty + j * 8) * K + k0 + tx;
        Th[p] = h; Tl[p] = l;
    }
}

// ---------------------------------------------------------------------------
// mma.sync GEMM (bf16x3 split precision) — R9: ldmatrix fragments,
// 2-stage pipeline, 2 CTAs/SM.
// CTA 128x128, 8 warps (2x4), warp tile 64x32, BK=32.
// ---------------------------------------------------------------------------
#define ROWB 80
#define COMP_BYTES (128 * ROWB)      // 10240
#define STAGE_BYTES (4 * COMP_BYTES) // 40960
#define GEMM_SMEM (2 * STAGE_BYTES)  // 81920

__global__ void __launch_bounds__(256, 2) gemm_mma(const __nv_bfloat16* __restrict__ Ahi,
                                                   const __nv_bfloat16* __restrict__ Alo,
                                                   const __nv_bfloat16* __restrict__ Bhi,
                                                   const __nv_bfloat16* __restrict__ Blo,
                                                   const float* __restrict__ bias,
                                                   float* __restrict__ C, int Ntot) {
    extern __shared__ char smem[];
    const uint32_t sbase = smem_u32(smem);

    int tid = threadIdx.x;
    int wid = tid >> 5, lane = tid & 31;
    int wm = wid >> 2, wn = wid & 3;
    int grp = lane >> 2, tig = lane & 3;
    const int lrow = lane & 15;              // ldmatrix row within 16-row group
    const int lc16 = (lane >> 4) * 16;       // ldmatrix 16B column select

    const int m0 = blockIdx.y * 128;
    const int n0 = blockIdx.x * 128;

    const __nv_bfloat16* gA[2] = { Ahi + (size_t)m0 * GK, Alo + (size_t)m0 * GK };
    const __nv_bfloat16* gB[2] = { Bhi + (size_t)n0 * GK, Blo + (size_t)n0 * GK };

    auto load_chunk = [&](int c, int st) {
        uint32_t sa = sbase + st * STAGE_BYTES;
        #pragma unroll
        for (int i = 0; i < 2; i++) {
            int id = tid + i * 256;
            int r = id >> 2;
            int q = id & 3;
            uint32_t dst = sa + (uint32_t)(r * ROWB + q * 16);
            size_t gsrc = (size_t)r * GK + c * KCHUNK + q * 8;
            CP_ASYNC16(dst + 0 * COMP_BYTES, gA[0] + gsrc);
            CP_ASYNC16(dst + 1 * COMP_BYTES, gA[1] + gsrc);
            CP_ASYNC16(dst + 2 * COMP_BYTES, gB[0] + gsrc);
            CP_ASYNC16(dst + 3 * COMP_BYTES, gB[1] + gsrc);
        }
        CP_COMMIT();
    };

    load_chunk(0, 0);
    load_chunk(1, 1);

    float acc[4][4][4];
    #pragma unroll
    for (int mi = 0; mi < 4; mi++)
        #pragma unroll
        for (int ni = 0; ni < 4; ni++)
            #pragma unroll
            for (int j = 0; j < 4; j++) acc[mi][ni][j] = 0.f;

    // ldmatrix base offsets (per-thread), within a component
    const uint32_t aOff = (uint32_t)(wm * 64 + lrow) * ROWB + lc16;
    const uint32_t bOff = (uint32_t)(wn * 32 + lrow) * ROWB + lc16;

    for (int c = 0; c < NCHUNK; c++) {
        if (c < NCHUNK - 1) CP_WAIT(1); else CP_WAIT(0);
        __syncthreads();

        uint32_t sa = sbase + (c & 1) * STAGE_BYTES;
        uint32_t sAh = sa, sAl = sa + COMP_BYTES;
        uint32_t sBh = sa + 2 * COMP_BYTES, sBl = sa + 3 * COMP_BYTES;

        #pragma unroll
        for (int s = 0; s < 2; s++) {
            const uint32_t ko = (uint32_t)s * 32;
            // B fragments: np in {0,1}, each x4 covers n-tiles 2np, 2np+1
            uint32_t bh[2][4], bl[2][4];
            #pragma unroll
            for (int np = 0; np < 2; np++) {
                uint32_t ba = bOff + (uint32_t)np * 16 * ROWB + ko;
                ldsm_x4(bh[np], sBh + ba);
                ldsm_x4(bl[np], sBl + ba);
            }
            #pragma unroll
            for (int mi = 0; mi < 4; mi++) {
                uint32_t ah[4], al[4];
                uint32_t aa = aOff + (uint32_t)mi * 16 * ROWB + ko;
                ldsm_x4(ah, sAh + aa);
                ldsm_x4(al, sAl + aa);
                #pragma unroll
                for (int ni = 0; ni < 4; ni++) {
                    int np = ni >> 1, hf = ni & 1;
                    uint32_t bhf[2] = { bh[np][hf], bh[np][2 + hf] };
                    uint32_t blf[2] = { bl[np][hf], bl[np][2 + hf] };
                    mma16816(acc[mi][ni], ah, bhf);
                    mma16816(acc[mi][ni], ah, blf);
                    mma16816(acc[mi][ni], al, bhf);
                }
            }
        }
        __syncthreads();
        if (c + 2 < NCHUNK) load_chunk(c + 2, c & 1);
    }

    #pragma unroll
    for (int mi = 0; mi < 4; mi++) {
        int row0 = m0 + wm * 64 + mi * 16 + grp;
        #pragma unroll
        for (int ni = 0; ni < 4; ni++) {
            int col = n0 + wn * 32 + ni * 8 + tig * 2;
            float bx = bias[col], by = bias[col + 1];
            float2* p0 = reinterpret_cast<float2*>(C + (size_t)row0 * Ntot + col);
            float2* p1 = reinterpret_cast<float2*>(C + (size_t)(row0 + 8) * Ntot + col);
            *p0 = make_float2(acc[mi][ni][0] + bx, acc[mi][ni][1] + by);
            *p1 = make_float2(acc[mi][ni][2] + bx, acc[mi][ni][3] + by);
        }
    }
}

// ---------------------------------------------------------------------------
// Prepass: fp32 QKV -> head-major bf16 hi/lo; Q pre-scaled; V transposed
// ---------------------------------------------------------------------------
__global__ void __launch_bounds__(256) prep_qkv(const float* __restrict__ qkv,
                                                __nv_bfloat16* __restrict__ qh,
                                                __nv_bfloat16* __restrict__ ql,
                                                __nv_bfloat16* __restrict__ kh,
                                                __nv_bfloat16* __restrict__ kl,
                                                __nv_bfloat16* __restrict__ vth,
                                                __nv_bfloat16* __restrict__ vtl) {
    __shared__ float vs[64][65];
    int st = blockIdx.x, h = blockIdx.y, b = blockIdx.z;
    int bh = b * HEADS + h;
    int s0 = st * 64;
    int tid = threadIdx.x;

    #pragma unroll
    for (int i = 0; i < 4; i++) {
        int id = tid + i * 256;              // 0..1023
        int row = id >> 4, c4 = (id & 15) * 4;
        const float* src = qkv + (size_t)(b * SEQ + s0 + row) * 3072 + h * 64 + c4;
        size_t dst = ((size_t)bh * SEQ + s0 + row) * 64 + c4;
        float4 qv = *reinterpret_cast<const float4*>(src);
        store_split2(qh + dst,     ql + dst,     qv.x * 0.125f, qv.y * 0.125f);
        store_split2(qh + dst + 2, ql + dst + 2, qv.z * 0.125f, qv.w * 0.125f);
        float4 kv = *reinterpret_cast<const float4*>(src + 1024);
        store_split2(kh + dst,     kl + dst,     kv.x, kv.y);
        store_split2(kh + dst + 2, kl + dst + 2, kv.z, kv.w);
        float4 vv = *reinterpret_cast<const float4*>(src + 2048);
        vs[row][c4 + 0] = vv.x; vs[row][c4 + 1] = vv.y;
        vs[row][c4 + 2] = vv.z; vs[row][c4 + 3] = vv.w;
    }
    __syncthreads();
    #pragma unroll
    for (int i = 0; i < 4; i++) {
        int id = tid + i * 256;
        int d = id >> 4, s4 = (id & 15) * 4;
        size_t dst = ((size_t)bh * HEAD_DIM + d) * SEQ + s0 + s4;
        store_split2(vth + dst,     vtl + dst,     vs[s4][d],     vs[s4 + 1][d]);
        store_split2(vth + dst + 2, vtl + dst + 2, vs[s4 + 2][d], vs[s4 + 3][d]);
    }
}

// ---------------------------------------------------------------------------
// Flash attention via mma.sync (bf16x3 split precision) — unchanged from R9
// ---------------------------------------------------------------------------
#define QT 128
#define KT 64
#define RSTR 144
#define SM_QBYTES (QT * RSTR)
#define SM_STAGE0 (2 * SM_QBYTES)
#define TILE_B (KT * RSTR)
#define STAGE_B (4 * TILE_B)
#define ATTN_SMEM (SM_STAGE0 + 2 * STAGE_B)

__global__ void __launch_bounds__(256, 1)
attn_mma(const __nv_bfloat16* __restrict__ qh, const __nv_bfloat16* __restrict__ ql,
         const __nv_bfloat16* __restrict__ kh, const __nv_bfloat16* __restrict__ kl,
         const __nv_bfloat16* __restrict__ vth, const __nv_bfloat16* __restrict__ vtl,
         __nv_bfloat16* __restrict__ oh, __nv_bfloat16* __restrict__ ol) {
    extern __shared__ char smem[];
    const uint32_t sb = smem_u32(smem);
    const int tid = threadIdx.x;
    const int w = tid >> 5, lane = tid & 31;
    const int grp = lane >> 2, tig = lane & 3;
    const int qt = blockIdx.x, h = blockIdx.y, b = blockIdx.z;
    const int bh = b * HEADS + h;
    const int q0 = qt * QT;

    const __nv_bfloat16* qsrc[2] = { qh + ((size_t)bh * SEQ + q0) * 64,
                                     ql + ((size_t)bh * SEQ + q0) * 64 };
    const __nv_bfloat16* ksrc[2] = { kh + (size_t)bh * SEQ * 64,
                                     kl + (size_t)bh * SEQ * 64 };
    const __nv_bfloat16* vsrc[2] = { vth + (size_t)bh * HEAD_DIM * SEQ,
                                     vtl + (size_t)bh * HEAD_DIM * SEQ };

    #pragma unroll
    for (int i = 0; i < 8; i++) {
        int id = tid + i * 256;
        int comp = id >> 10, rem = id & 1023;
        int row = rem >> 3, qq = rem & 7;
        CP_ASYNC16(sb + comp * SM_QBYTES + row * RSTR + qq * 16,
                   qsrc[comp] + (size_t)row * 64 + qq * 8);
    }
    CP_COMMIT();

    auto load_kv = [&](int kt_, int stg) {
        uint32_t sa = sb + SM_STAGE0 + stg * STAGE_B;
        #pragma unroll
        for (int i = 0; i < 8; i++) {
            int id = tid + i * 256;
            int arr = id >> 9, rem = id & 511;
            int row = rem >> 3, qq = rem & 7;
            uint32_t dst = sa + arr * TILE_B + row * RSTR + qq * 16;
            const __nv_bfloat16* src;
            if (arr == 0)      src = ksrc[0] + (size_t)(kt_ + row) * 64 + qq * 8;
            else if (arr == 1) src = ksrc[1] + (size_t)(kt_ + row) * 64 + qq * 8;
            else if (arr == 2) src = vsrc[0] + (size_t)row * SEQ + kt_ + qq * 8;
            else               src = vsrc[1] + (size_t)row * SEQ + kt_ + qq * 8;
            CP_ASYNC16(dst, src);
        }
        CP_COMMIT();
    };

    load_kv(0, 0);
    load_kv(KT, 1);

    CP_WAIT(2);
    __syncthreads();

    uint32_t qfh[4][4], qfl[4][4];
    {
        int arow = w * 16 + ((lane >> 3) & 1) * 8 + (lane & 7);
        int acol = (lane >> 4) * 16;
        #pragma unroll
        for (int j = 0; j < 4; j++) {
            ldsm_x4(qfh[j], sb + arow * RSTR + j * 32 + acol);
            ldsm_x4(qfl[j], sb + SM_QBYTES + arow * RSTR + j * 32 + acol);
        }
    }

    float m0 = -1e30f, m1 = -1e30f, l0 = 0.f, l1 = 0.f;
    float oacc[8][4];
    #pragma unroll
    for (int ni = 0; ni < 8; ni++)
        #pragma unroll
        for (int j = 0; j < 4; j++) oacc[ni][j] = 0.f;

    const int brow = (lane >> 4) * 8 + (lane & 7);
    const int bcol = ((lane >> 3) & 1) * 16;

    for (int c = 0; c < SEQ / KT; c++) {
        if (c < SEQ / KT - 1) CP_WAIT(1); else CP_WAIT(0);
        __syncthreads();
        uint32_t sa = sb + SM_STAGE0 + (c & 1) * STAGE_B;
        uint32_t sKh = sa, sKl = sa + TILE_B;
        uint32_t sVh = sa + 2 * TILE_B, sVl = sa + 3 * TILE_B;

        float sacc[8][4];
        #pragma unroll
        for (int ni = 0; ni < 8; ni++)
            #pragma unroll
            for (int j = 0; j < 4; j++) sacc[ni][j] = 0.f;

        #pragma unroll
        for (int j = 0; j < 4; j++) {
            #pragma unroll
            for (int g = 0; g < 4; g++) {
                uint32_t kb[4], kb2[4];
                ldsm_x4(kb, sKh + (uint32_t)(g * 16 + brow) * RSTR + j * 32 + bcol);
                mma16816(sacc[2 * g],     qfh[j], kb);
                mma16816(sacc[2 * g + 1], qfh[j], kb + 2);
                mma16816(sacc[2 * g],     qfl[j], kb);
                mma16816(sacc[2 * g + 1], qfl[j], kb + 2);
                ldsm_x4(kb2, sKl + (uint32_t)(g * 16 + brow) * RSTR + j * 32 + bcol);
                mma16816(sacc[2 * g],     qfh[j], kb2);
                mma16816(sacc[2 * g + 1], qfh[j], kb2 + 2);
            }
        }

        float mx0 = -1e30f, mx1 = -1e30f;
        #pragma unroll
        for (int ni = 0; ni < 8; ni++) {
            mx0 = fmaxf(mx0, fmaxf(sacc[ni][0], sacc[ni][1]));
            mx1 = fmaxf(mx1, fmaxf(sacc[ni][2], sacc[ni][3]));
        }
        mx0 = fmaxf(mx0, __shfl_xor_sync(0xffffffffu, mx0, 1));
        mx0 = fmaxf(mx0, __shfl_xor_sync(0xffffffffu, mx0, 2));
        mx1 = fmaxf(mx1, __shfl_xor_sync(0xffffffffu, mx1, 1));
        mx1 = fmaxf(mx1, __shfl_xor_sync(0xffffffffu, mx1, 2));
        float mn0 = fmaxf(m0, mx0), mn1 = fmaxf(m1, mx1);
        float al0 = __expf(m0 - mn0), al1 = __expf(m1 - mn1);
        m0 = mn0; m1 = mn1;
        float rs0 = 0.f, rs1 = 0.f;
        #pragma unroll
        for (int ni = 0; ni < 8; ni++) {
            sacc[ni][0] = __expf(sacc[ni][0] - mn0);
            sacc[ni][1] = __expf(sacc[ni][1] - mn0);
            sacc[ni][2] = __expf(sacc[ni][2] - mn1);
            sacc[ni][3] = __expf(sacc[ni][3] - mn1);
            rs0 += sacc[ni][0] + sacc[ni][1];
            rs1 += sacc[ni][2] + sacc[ni][3];
        }
        rs0 += __shfl_xor_sync(0xffffffffu, rs0, 1);
        rs0 += __shfl_xor_sync(0xffffffffu, rs0, 2);
        rs1 += __shfl_xor_sync(0xffffffffu, rs1, 1);
        rs1 += __shfl_xor_sync(0xffffffffu, rs1, 2);
        l0 = l0 * al0 + rs0;
        l1 = l1 * al1 + rs1;

        #pragma unroll
        for (int ni = 0; ni < 8; ni++) {
            oacc[ni][0] *= al0; oacc[ni][1] *= al0;
            oacc[ni][2] *= al1; oacc[ni][3] *= al1;
        }

        #pragma unroll
        for (int j = 0; j < 4; j++) {
            uint32_t phf[4], plf[4];
            split_pack(sacc[2 * j][0],     sacc[2 * j][1],     phf[0], plf[0]);
            split_pack(sacc[2 * j][2],     sacc[2 * j][3],     phf[1], plf[1]);
            split_pack(sacc[2 * j + 1][0], sacc[2 * j + 1][1], phf[2], plf[2]);
            split_pack(sacc[2 * j + 1][2], sacc[2 * j + 1][3], phf[3], plf[3]);
            #pragma unroll
            for (int g = 0; g < 4; g++) {
                uint32_t vb[4], vb2[4];
                ldsm_x4(vb, sVh + (uint32_t)(g * 16 + brow) * RSTR + j * 32 + bcol);
                mma16816(oacc[2 * g],     phf, vb);
                mma16816(oacc[2 * g + 1], phf, vb + 2);
                mma16816(oacc[2 * g],     plf, vb);
                mma16816(oacc[2 * g + 1], plf, vb + 2);
                ldsm_x4(vb2, sVl + (uint32_t)(g * 16 + brow) * RSTR + j * 32 + bcol);
                mma16816(oacc[2 * g],     phf, vb2);
                mma16816(oacc[2 * g + 1], phf, vb2 + 2);
            }
        }

        __syncthreads();
        if (c + 2 < SEQ / KT) load_kv((c + 2) * KT, c & 1);
    }

    float inv0 = 1.f / l0, inv1 = 1.f / l1;
    int row0 = q0 + w * 16 + grp;
    size_t ob0 = ((size_t)(b * SEQ) + row0) * INNER + h * 64;
    size_t ob1 = ob0 + 8 * INNER;
    #pragma unroll
    for (int ni = 0; ni < 8; ni++) {
        int col = ni * 8 + tig * 2;
        store_split2(oh + ob0 + col, ol + ob0 + col,
                     oacc[ni][0] * inv0, oacc[ni][1] * inv0);
        store_split2(oh + ob1 + col, ol + ob1 + col,
                     oacc[ni][2] * inv1, oacc[ni][3] * inv1);
    }
}

// ---------------------------------------------------------------------------
extern "C" void kernel_launch(void* const* d_in, const int* in_sizes, int n_in,
                              void* d_out, int out_size) {
    const float* x     = (const float*)d_in[0];
    const float* ln_g  = (const float*)d_in[1];
    const float* ln_b  = (const float*)d_in[2];
    const float* w_qkv = (const float*)d_in[3];
    const float* b_qkv = (const float*)d_in[4];
    const float* w_out = (const float*)d_in[5];
    const float* b_out = (const float*)d_in[6];
    float* out = (float*)d_out;

    __nv_bfloat16 *xnh, *xnl, *wqh, *wql, *woh, *wol, *ath, *atl;
    __nv_bfloat16 *qh, *ql, *kh, *kl, *vth, *vtl;
    float* qkvb;
    cudaGetSymbolAddress((void**)&xnh, g_xnh);
    cudaGetSymbolAddress((void**)&xnl, g_xnl);
    cudaGetSymbolAddress((void**)&wqh, g_wqh);
    cudaGetSymbolAddress((void**)&wql, g_wql);
    cudaGetSymbolAddress((void**)&woh, g_woh);
    cudaGetSymbolAddress((void**)&wol, g_wol);
    cudaGetSymbolAddress((void**)&ath, g_ath);
    cudaGetSymbolAddress((void**)&atl, g_atl);
    cudaGetSymbolAddress((void**)&qkvb, g_qkv);
    cudaGetSymbolAddress((void**)&qh,  g_qh);
    cudaGetSymbolAddress((void**)&ql,  g_ql);
    cudaGetSymbolAddress((void**)&kh,  g_kh);
    cudaGetSymbolAddress((void**)&kl,  g_kl);
    cudaGetSymbolAddress((void**)&vth, g_vth);
    cudaGetSymbolAddress((void**)&vtl, g_vtl);

    cudaFuncSetAttribute(gemm_mma, cudaFuncAttributeMaxDynamicSharedMemorySize,
                         GEMM_SMEM);
    cudaFuncSetAttribute(attn_mma, cudaFuncAttributeMaxDynamicSharedMemorySize,
                         ATTN_SMEM);

    ln_kernel<<<TOKENS, 256>>>(x, ln_g, ln_b, xnh, xnl);
    transpose_split<<<dim3(3 * INNER / 32, DIMX / 32), dim3(32, 8)>>>(
        w_qkv, wqh, wql, DIMX, 3 * INNER);
    transpose_split<<<dim3(DIMX / 32, INNER / 32), dim3(32, 8)>>>(
        w_out, woh, wol, INNER, DIMX);
    gemm_mma<<<dim3(3 * INNER / 128, TOKENS / 128), 256, GEMM_SMEM>>>(
        xnh, xnl, wqh, wql, b_qkv, qkvb, 3 * INNER);
    prep_qkv<<<dim3(SEQ / 64, HEADS, BATCH), 256>>>(
        qkvb, qh, ql, kh, kl, vth, vtl);
    attn_mma<<<dim3(SEQ / QT, HEADS, BATCH), 256, ATTN_SMEM>>>(
        qh, ql, kh, kl, vth, vtl, ath, atl);
    gemm_mma<<<dim3(DIMX / 128, TOKENS / 128), 256, GEMM_SMEM>>>(
        ath, atl, woh, wol, b_out, out, DIMX);
}

// round 13
// speedup vs baseline: 2.8743x; 1.0161x over previous
#include <cuda_runtime.h>
#include <cuda_bf16.h>
#include <cstdint>

#define DIMX 1024
#define TOKENS 8192
#define INNER 1024
#define HEADS 16
#define HEAD_DIM 64
#define SEQ 2048
#define BATCH 4
#define GK 1024
#define KCHUNK 32
#define NCHUNK (GK / KCHUNK)

// ---------------------------------------------------------------------------
// Scratch
// ---------------------------------------------------------------------------
__device__ __nv_bfloat16 g_xnh[TOKENS * DIMX];
__device__ __nv_bfloat16 g_xnl[TOKENS * DIMX];
__device__ __nv_bfloat16 g_wqh[3 * INNER * DIMX];
__device__ __nv_bfloat16 g_wql[3 * INNER * DIMX];
__device__ __nv_bfloat16 g_woh[DIMX * INNER];
__device__ __nv_bfloat16 g_wol[DIMX * INNER];
__device__ float         g_qkv[TOKENS * 3 * INNER];
__device__ __nv_bfloat16 g_ath[TOKENS * INNER];
__device__ __nv_bfloat16 g_atl[TOKENS * INNER];
// head-major split QKV for attention
__device__ __nv_bfloat16 g_qh[BATCH * HEADS * SEQ * HEAD_DIM];
__device__ __nv_bfloat16 g_ql[BATCH * HEADS * SEQ * HEAD_DIM];
__device__ __nv_bfloat16 g_kh[BATCH * HEADS * SEQ * HEAD_DIM];
__device__ __nv_bfloat16 g_kl[BATCH * HEADS * SEQ * HEAD_DIM];
__device__ __nv_bfloat16 g_vth[BATCH * HEADS * HEAD_DIM * SEQ];  // [bh][d][s]
__device__ __nv_bfloat16 g_vtl[BATCH * HEADS * HEAD_DIM * SEQ];

// ---------------------------------------------------------------------------
// Helpers (base ISA only — target is bare sm_103)
// ---------------------------------------------------------------------------
__device__ __forceinline__ uint32_t smem_u32(const void* p) {
    uint32_t a;
    asm("{ .reg .u64 t; cvta.to.shared.u64 t, %1; cvt.u32.u64 %0, t; }" : "=r"(a) : "l"(p));
    return a;
}
#define CP_ASYNC16(dst, src) \
    asm volatile("cp.async.cg.shared.global [%0], [%1], 16;" :: "r"(dst), "l"(src) : "memory")
#define CP_COMMIT() asm volatile("cp.async.commit_group;" ::: "memory")
#define CP_WAIT(n)  asm volatile("cp.async.wait_group %0;" :: "n"(n) : "memory")

__device__ __forceinline__ void ldsm_x4(uint32_t* r, uint32_t addr) {
    asm volatile("ldmatrix.sync.aligned.m8n8.x4.shared.b16 {%0,%1,%2,%3}, [%4];"
                 : "=r"(r[0]), "=r"(r[1]), "=r"(r[2]), "=r"(r[3]) : "r"(addr));
}
// NOTE: non-volatile — pure register computation; deps carried by "+f".
// Lets ptxas interleave independent MMA chains.
__device__ __forceinline__ void mma16816(float* c, const uint32_t* a, const uint32_t* b) {
    asm("mma.sync.aligned.m16n8k16.row.col.f32.bf16.bf16.f32 "
        "{%0,%1,%2,%3}, {%4,%5,%6,%7}, {%8,%9}, {%0,%1,%2,%3};"
        : "+f"(c[0]), "+f"(c[1]), "+f"(c[2]), "+f"(c[3])
        : "r"(a[0]), "r"(a[1]), "r"(a[2]), "r"(a[3]), "r"(b[0]), "r"(b[1]));
}
__device__ __forceinline__ void split_bf(float v, __nv_bfloat16& h, __nv_bfloat16& l) {
    h = __float2bfloat16_rn(v);
    l = __float2bfloat16_rn(v - __bfloat162float(h));
}
__device__ __forceinline__ void split_pack(float a, float b, uint32_t& hi, uint32_t& lo) {
    __nv_bfloat16 ha = __float2bfloat16_rn(a), hb = __float2bfloat16_rn(b);
    __nv_bfloat162 hp = __halves2bfloat162(ha, hb);
    hi = *reinterpret_cast<uint32_t*>(&hp);
    __nv_bfloat162 lp = __halves2bfloat162(
        __float2bfloat16_rn(a - __bfloat162float(ha)),
        __float2bfloat16_rn(b - __bfloat162float(hb)));
    lo = *reinterpret_cast<uint32_t*>(&lp);
}
__device__ __forceinline__ void store_split2(__nv_bfloat16* ph, __nv_bfloat16* pl,
                                             float a, float b) {
    __nv_bfloat16 ha, la, hb, lb;
    split_bf(a, ha, la); split_bf(b, hb, lb);
    *reinterpret_cast<__nv_bfloat162*>(ph) = __halves2bfloat162(ha, hb);
    *reinterpret_cast<__nv_bfloat162*>(pl) = __halves2bfloat162(la, lb);
}

// ---------------------------------------------------------------------------
// LayerNorm -> bf16 hi/lo
// ---------------------------------------------------------------------------
__global__ void __launch_bounds__(256) ln_kernel(const float* __restrict__ x,
                                                 const float* __restrict__ g,
                                                 const float* __restrict__ b,
                                                 __nv_bfloat16* __restrict__ oh,
                                                 __nv_bfloat16* __restrict__ ol) {
    int row = blockIdx.x;
    int t = threadIdx.x;
    float4 v = reinterpret_cast<const float4*>(x + (size_t)row * DIMX)[t];
    float s = v.x + v.y + v.z + v.w;
    float s2 = v.x * v.x + v.y * v.y + v.z * v.z + v.w * v.w;
    #pragma unroll
    for (int o = 16; o; o >>= 1) {
        s  += __shfl_xor_sync(0xffffffffu, s,  o);
        s2 += __shfl_xor_sync(0xffffffffu, s2, o);
    }
    __shared__ float ws[8], ws2[8];
    int w = t >> 5, l = t & 31;
    if (l == 0) { ws[w] = s; ws2[w] = s2; }
    __syncthreads();
    float sum = 0.f, sum2 = 0.f;
    #pragma unroll
    for (int i = 0; i < 8; i++) { sum += ws[i]; sum2 += ws2[i]; }
    float mu = sum * (1.0f / DIMX);
    float var = sum2 * (1.0f / DIMX) - mu * mu;
    float rstd = rsqrtf(var + 1e-5f);

    float4 gv = reinterpret_cast<const float4*>(g)[t];
    float4 bv = reinterpret_cast<const float4*>(b)[t];
    float o0 = (v.x - mu) * rstd * gv.x + bv.x;
    float o1 = (v.y - mu) * rstd * gv.y + bv.y;
    float o2 = (v.z - mu) * rstd * gv.z + bv.z;
    float o3 = (v.w - mu) * rstd * gv.w + bv.w;
    size_t p = (size_t)row * DIMX + t * 4;
    store_split2(oh + p, ol + p, o0, o1);
    store_split2(oh + p + 2, ol + p + 2, o2, o3);
}

// ---------------------------------------------------------------------------
// Weight transpose + split
// ---------------------------------------------------------------------------
__global__ void __launch_bounds__(256) transpose_split(const float* __restrict__ W,
                                                       __nv_bfloat16* __restrict__ Th,
                                                       __nv_bfloat16* __restrict__ Tl,
                                                       int K, int N) {
    __shared__ float tile[32][33];
    int n0 = blockIdx.x * 32, k0 = blockIdx.y * 32;
    int tx = threadIdx.x, ty = threadIdx.y;
    #pragma unroll
    for (int j = 0; j < 4; j++)
        tile[ty + j * 8][tx] = W[(size_t)(k0 + ty + j * 8) * N + n0 + tx];
    __syncthreads();
    #pragma unroll
    for (int j = 0; j < 4; j++) {
        float v = tile[tx][ty + j * 8];
        __nv_bfloat16 h, l;
        split_bf(v, h, l);
        size_t p = (size_t)(n0 + ty + j * 8) * K + k0 + tx;
        Th[p] = h; Tl[p] = l;
    }
}

// ---------------------------------------------------------------------------
// mma.sync GEMM (bf16x3) — R12: combo-major MMA order (dependent distance 4)
// ---------------------------------------------------------------------------
#define ROWB 80
#define COMP_BYTES (128 * ROWB)
#define STAGE_BYTES (4 * COMP_BYTES)
#define GEMM_SMEM (2 * STAGE_BYTES)

__global__ void __launch_bounds__(256, 2) gemm_mma(const __nv_bfloat16* __restrict__ Ahi,
                                                   const __nv_bfloat16* __restrict__ Alo,
                                                   const __nv_bfloat16* __restrict__ Bhi,
                                                   const __nv_bfloat16* __restrict__ Blo,
                                                   const float* __restrict__ bias,
                                                   float* __restrict__ C, int Ntot) {
    extern __shared__ char smem[];
    const uint32_t sbase = smem_u32(smem);

    int tid = threadIdx.x;
    int wid = tid >> 5, lane = tid & 31;
    int wm = wid >> 2, wn = wid & 3;
    int grp = lane >> 2, tig = lane & 3;
    const int lrow = lane & 15;
    const int lc16 = (lane >> 4) * 16;

    const int m0 = blockIdx.y * 128;
    const int n0 = blockIdx.x * 128;

    const __nv_bfloat16* gA[2] = { Ahi + (size_t)m0 * GK, Alo + (size_t)m0 * GK };
    const __nv_bfloat16* gB[2] = { Bhi + (size_t)n0 * GK, Blo + (size_t)n0 * GK };

    auto load_chunk = [&](int c, int st) {
        uint32_t sa = sbase + st * STAGE_BYTES;
        #pragma unroll
        for (int i = 0; i < 2; i++) {
            int id = tid + i * 256;
            int r = id >> 2;
            int q = id & 3;
            uint32_t dst = sa + (uint32_t)(r * ROWB + q * 16);
            size_t gsrc = (size_t)r * GK + c * KCHUNK + q * 8;
            CP_ASYNC16(dst + 0 * COMP_BYTES, gA[0] + gsrc);
            CP_ASYNC16(dst + 1 * COMP_BYTES, gA[1] + gsrc);
            CP_ASYNC16(dst + 2 * COMP_BYTES, gB[0] + gsrc);
            CP_ASYNC16(dst + 3 * COMP_BYTES, gB[1] + gsrc);
        }
        CP_COMMIT();
    };

    load_chunk(0, 0);
    load_chunk(1, 1);

    float acc[4][4][4];
    #pragma unroll
    for (int mi = 0; mi < 4; mi++)
        #pragma unroll
        for (int ni = 0; ni < 4; ni++)
            #pragma unroll
            for (int j = 0; j < 4; j++) acc[mi][ni][j] = 0.f;

    const uint32_t aOff = (uint32_t)(wm * 64 + lrow) * ROWB + lc16;
    const uint32_t bOff = (uint32_t)(wn * 32 + lrow) * ROWB + lc16;

    for (int c = 0; c < NCHUNK; c++) {
        if (c < NCHUNK - 1) CP_WAIT(1); else CP_WAIT(0);
        __syncthreads();

        uint32_t sa = sbase + (c & 1) * STAGE_BYTES;
        uint32_t sAh = sa, sAl = sa + COMP_BYTES;
        uint32_t sBh = sa + 2 * COMP_BYTES, sBl = sa + 3 * COMP_BYTES;

        #pragma unroll
        for (int s = 0; s < 2; s++) {
            const uint32_t ko = (uint32_t)s * 32;
            uint32_t bh[2][4], bl[2][4];
            #pragma unroll
            for (int np = 0; np < 2; np++) {
                uint32_t ba = bOff + (uint32_t)np * 16 * ROWB + ko;
                ldsm_x4(bh[np], sBh + ba);
                ldsm_x4(bl[np], sBl + ba);
            }
            #pragma unroll
            for (int mi = 0; mi < 4; mi++) {
                uint32_t ah[4], al[4];
                uint32_t aa = aOff + (uint32_t)mi * 16 * ROWB + ko;
                ldsm_x4(ah, sAh + aa);
                ldsm_x4(al, sAl + aa);
                // combo-major: all 4 independent acc tiles per combo
                #pragma unroll
                for (int ni = 0; ni < 4; ni++) {
                    uint32_t bf[2] = { bh[ni >> 1][ni & 1], bh[ni >> 1][2 + (ni & 1)] };
                    mma16816(acc[mi][ni], ah, bf);
                }
                #pragma unroll
                for (int ni = 0; ni < 4; ni++) {
                    uint32_t bf[2] = { bl[ni >> 1][ni & 1], bl[ni >> 1][2 + (ni & 1)] };
                    mma16816(acc[mi][ni], ah, bf);
                }
                #pragma unroll
                for (int ni = 0; ni < 4; ni++) {
                    uint32_t bf[2] = { bh[ni >> 1][ni & 1], bh[ni >> 1][2 + (ni & 1)] };
                    mma16816(acc[mi][ni], al, bf);
                }
            }
        }
        __syncthreads();
        if (c + 2 < NCHUNK) load_chunk(c + 2, c & 1);
    }

    #pragma unroll
    for (int mi = 0; mi < 4; mi++) {
        int row0 = m0 + wm * 64 + mi * 16 + grp;
        #pragma unroll
        for (int ni = 0; ni < 4; ni++) {
            int col = n0 + wn * 32 + ni * 8 + tig * 2;
            float bx = bias[col], by = bias[col + 1];
            float2* p0 = reinterpret_cast<float2*>(C + (size_t)row0 * Ntot + col);
            float2* p1 = reinterpret_cast<float2*>(C + (size_t)(row0 + 8) * Ntot + col);
            *p0 = make_float2(acc[mi][ni][0] + bx, acc[mi][ni][1] + by);
            *p1 = make_float2(acc[mi][ni][2] + bx, acc[mi][ni][3] + by);
        }
    }
}

// ---------------------------------------------------------------------------
// Prepass: fp32 QKV -> head-major bf16 hi/lo; Q pre-scaled; V transposed
// ---------------------------------------------------------------------------
__global__ void __launch_bounds__(256) prep_qkv(const float* __restrict__ qkv,
                                                __nv_bfloat16* __restrict__ qh,
                                                __nv_bfloat16* __restrict__ ql,
                                                __nv_bfloat16* __restrict__ kh,
                                                __nv_bfloat16* __restrict__ kl,
                                                __nv_bfloat16* __restrict__ vth,
                                                __nv_bfloat16* __restrict__ vtl) {
    __shared__ float vs[64][65];
    int st = blockIdx.x, h = blockIdx.y, b = blockIdx.z;
    int bh = b * HEADS + h;
    int s0 = st * 64;
    int tid = threadIdx.x;

    #pragma unroll
    for (int i = 0; i < 4; i++) {
        int id = tid + i * 256;
        int row = id >> 4, c4 = (id & 15) * 4;
        const float* src = qkv + (size_t)(b * SEQ + s0 + row) * 3072 + h * 64 + c4;
        size_t dst = ((size_t)bh * SEQ + s0 + row) * 64 + c4;
        float4 qv = *reinterpret_cast<const float4*>(src);
        store_split2(qh + dst,     ql + dst,     qv.x * 0.125f, qv.y * 0.125f);
        store_split2(qh + dst + 2, ql + dst + 2, qv.z * 0.125f, qv.w * 0.125f);
        float4 kv = *reinterpret_cast<const float4*>(src + 1024);
        store_split2(kh + dst,     kl + dst,     kv.x, kv.y);
        store_split2(kh + dst + 2, kl + dst + 2, kv.z, kv.w);
        float4 vv = *reinterpret_cast<const float4*>(src + 2048);
        vs[row][c4 + 0] = vv.x; vs[row][c4 + 1] = vv.y;
        vs[row][c4 + 2] = vv.z; vs[row][c4 + 3] = vv.w;
    }
    __syncthreads();
    #pragma unroll
    for (int i = 0; i < 4; i++) {
        int id = tid + i * 256;
        int d = id >> 4, s4 = (id & 15) * 4;
        size_t dst = ((size_t)bh * HEAD_DIM + d) * SEQ + s0 + s4;
        store_split2(vth + dst,     vtl + dst,     vs[s4][d],     vs[s4 + 1][d]);
        store_split2(vth + dst + 2, vtl + dst + 2, vs[s4 + 2][d], vs[s4 + 3][d]);
    }
}

// ---------------------------------------------------------------------------
// Flash attention via mma.sync (bf16x3) — combo-major MMA order
// ---------------------------------------------------------------------------
#define QT 128
#define KT 64
#define RSTR 144
#define SM_QBYTES (QT * RSTR)
#define SM_STAGE0 (2 * SM_QBYTES)
#define TILE_B (KT * RSTR)
#define STAGE_B (4 * TILE_B)
#define ATTN_SMEM (SM_STAGE0 + 2 * STAGE_B)

__global__ void __launch_bounds__(256, 1)
attn_mma(const __nv_bfloat16* __restrict__ qh, const __nv_bfloat16* __restrict__ ql,
         const __nv_bfloat16* __restrict__ kh, const __nv_bfloat16* __restrict__ kl,
         const __nv_bfloat16* __restrict__ vth, const __nv_bfloat16* __restrict__ vtl,
         __nv_bfloat16* __restrict__ oh, __nv_bfloat16* __restrict__ ol) {
    extern __shared__ char smem[];
    const uint32_t sb = smem_u32(smem);
    const int tid = threadIdx.x;
    const int w = tid >> 5, lane = tid & 31;
    const int grp = lane >> 2, tig = lane & 3;
    const int qt = blockIdx.x, h = blockIdx.y, b = blockIdx.z;
    const int bh = b * HEADS + h;
    const int q0 = qt * QT;

    const __nv_bfloat16* qsrc[2] = { qh + ((size_t)bh * SEQ + q0) * 64,
                                     ql + ((size_t)bh * SEQ + q0) * 64 };
    const __nv_bfloat16* ksrc[2] = { kh + (size_t)bh * SEQ * 64,
                                     kl + (size_t)bh * SEQ * 64 };
    const __nv_bfloat16* vsrc[2] = { vth + (size_t)bh * HEAD_DIM * SEQ,
                                     vtl + (size_t)bh * HEAD_DIM * SEQ };

    #pragma unroll
    for (int i = 0; i < 8; i++) {
        int id = tid + i * 256;
        int comp = id >> 10, rem = id & 1023;
        int row = rem >> 3, qq = rem & 7;
        CP_ASYNC16(sb + comp * SM_QBYTES + row * RSTR + qq * 16,
                   qsrc[comp] + (size_t)row * 64 + qq * 8);
    }
    CP_COMMIT();

    auto load_kv = [&](int kt_, int stg) {
        uint32_t sa = sb + SM_STAGE0 + stg * STAGE_B;
        #pragma unroll
        for (int i = 0; i < 8; i++) {
            int id = tid + i * 256;
            int arr = id >> 9, rem = id & 511;
            int row = rem >> 3, qq = rem & 7;
            uint32_t dst = sa + arr * TILE_B + row * RSTR + qq * 16;
            const __nv_bfloat16* src;
            if (arr == 0)      src = ksrc[0] + (size_t)(kt_ + row) * 64 + qq * 8;
            else if (arr == 1) src = ksrc[1] + (size_t)(kt_ + row) * 64 + qq * 8;
            else if (arr == 2) src = vsrc[0] + (size_t)row * SEQ + kt_ + qq * 8;
            else               src = vsrc[1] + (size_t)row * SEQ + kt_ + qq * 8;
            CP_ASYNC16(dst, src);
        }
        CP_COMMIT();
    };

    load_kv(0, 0);
    load_kv(KT, 1);

    CP_WAIT(2);
    __syncthreads();

    uint32_t qfh[4][4], qfl[4][4];
    {
        int arow = w * 16 + ((lane >> 3) & 1) * 8 + (lane & 7);
        int acol = (lane >> 4) * 16;
        #pragma unroll
        for (int j = 0; j < 4; j++) {
            ldsm_x4(qfh[j], sb + arow * RSTR + j * 32 + acol);
            ldsm_x4(qfl[j], sb + SM_QBYTES + arow * RSTR + j * 32 + acol);
        }
    }

    float m0 = -1e30f, m1 = -1e30f, l0 = 0.f, l1 = 0.f;
    float oacc[8][4];
    #pragma unroll
    for (int ni = 0; ni < 8; ni++)
        #pragma unroll
        for (int j = 0; j < 4; j++) oacc[ni][j] = 0.f;

    const int brow = (lane >> 4) * 8 + (lane & 7);
    const int bcol = ((lane >> 3) & 1) * 16;

    for (int c = 0; c < SEQ / KT; c++) {
        if (c < SEQ / KT - 1) CP_WAIT(1); else CP_WAIT(0);
        __syncthreads();
        uint32_t sa = sb + SM_STAGE0 + (c & 1) * STAGE_B;
        uint32_t sKh = sa, sKl = sa + TILE_B;
        uint32_t sVh = sa + 2 * TILE_B, sVl = sa + 3 * TILE_B;

        float sacc[8][4];
        #pragma unroll
        for (int ni = 0; ni < 8; ni++)
            #pragma unroll
            for (int j = 0; j < 4; j++) sacc[ni][j] = 0.f;

        // S = Q K^T : per k16-step load all fragments, then 3 combo passes
        #pragma unroll
        for (int j = 0; j < 4; j++) {
            uint32_t kbh[4][4], kbl[4][4];
            #pragma unroll
            for (int g = 0; g < 4; g++) {
                uint32_t ba = (uint32_t)(g * 16 + brow) * RSTR + j * 32 + bcol;
                ldsm_x4(kbh[g], sKh + ba);
                ldsm_x4(kbl[g], sKl + ba);
            }
            #pragma unroll
            for (int g = 0; g < 4; g++) {
                mma16816(sacc[2 * g],     qfh[j], kbh[g]);
                mma16816(sacc[2 * g + 1], qfh[j], kbh[g] + 2);
            }
            #pragma unroll
            for (int g = 0; g < 4; g++) {
                mma16816(sacc[2 * g],     qfl[j], kbh[g]);
                mma16816(sacc[2 * g + 1], qfl[j], kbh[g] + 2);
            }
            #pragma unroll
            for (int g = 0; g < 4; g++) {
                mma16816(sacc[2 * g],     qfh[j], kbl[g]);
                mma16816(sacc[2 * g + 1], qfh[j], kbl[g] + 2);
            }
        }

        float mx0 = -1e30f, mx1 = -1e30f;
        #pragma unroll
        for (int ni = 0; ni < 8; ni++) {
            mx0 = fmaxf(mx0, fmaxf(sacc[ni][0], sacc[ni][1]));
            mx1 = fmaxf(mx1, fmaxf(sacc[ni][2], sacc[ni][3]));
        }
        mx0 = fmaxf(mx0, __shfl_xor_sync(0xffffffffu, mx0, 1));
        mx0 = fmaxf(mx0, __shfl_xor_sync(0xffffffffu, mx0, 2));
        mx1 = fmaxf(mx1, __shfl_xor_sync(0xffffffffu, mx1, 1));
        mx1 = fmaxf(mx1, __shfl_xor_sync(0xffffffffu, mx1, 2));
        float mn0 = fmaxf(m0, mx0), mn1 = fmaxf(m1, mx1);
        float al0 = __expf(m0 - mn0), al1 = __expf(m1 - mn1);
        m0 = mn0; m1 = mn1;
        float rs0 = 0.f, rs1 = 0.f;
        #pragma unroll
        for (int ni = 0; ni < 8; ni++) {
            sacc[ni][0] = __expf(sacc[ni][0] - mn0);
            sacc[ni][1] = __expf(sacc[ni][1] - mn0);
            sacc[ni][2] = __expf(sacc[ni][2] - mn1);
            sacc[ni][3] = __expf(sacc[ni][3] - mn1);
            rs0 += sacc[ni][0] + sacc[ni][1];
            rs1 += sacc[ni][2] + sacc[ni][3];
        }
        rs0 += __shfl_xor_sync(0xffffffffu, rs0, 1);
        rs0 += __shfl_xor_sync(0xffffffffu, rs0, 2);
        rs1 += __shfl_xor_sync(0xffffffffu, rs1, 1);
        rs1 += __shfl_xor_sync(0xffffffffu, rs1, 2);
        l0 = l0 * al0 + rs0;
        l1 = l1 * al1 + rs1;

        #pragma unroll
        for (int ni = 0; ni < 8; ni++) {
            oacc[ni][0] *= al0; oacc[ni][1] *= al0;
            oacc[ni][2] *= al1; oacc[ni][3] *= al1;
        }

        // O += P V : per k16-step, combo-major passes
        #pragma unroll
        for (int j = 0; j < 4; j++) {
            uint32_t phf[4], plf[4];
            split_pack(sacc[2 * j][0],     sacc[2 * j][1],     phf[0], plf[0]);
            split_pack(sacc[2 * j][2],     sacc[2 * j][3],     phf[1], plf[1]);
            split_pack(sacc[2 * j + 1][0], sacc[2 * j + 1][1], phf[2], plf[2]);
            split_pack(sacc[2 * j + 1][2], sacc[2 * j + 1][3], phf[3], plf[3]);
            uint32_t vbh[4][4], vbl[4][4];
            #pragma unroll
            for (int g = 0; g < 4; g++) {
                uint32_t ba = (uint32_t)(g * 16 + brow) * RSTR + j * 32 + bcol;
                ldsm_x4(vbh[g], sVh + ba);
                ldsm_x4(vbl[g], sVl + ba);
            }
            #pragma unroll
            for (int g = 0; g < 4; g++) {
                mma16816(oacc[2 * g],     phf, vbh[g]);
                mma16816(oacc[2 * g + 1], phf, vbh[g] + 2);
            }
            #pragma unroll
            for (int g = 0; g < 4; g++) {
                mma16816(oacc[2 * g],     plf, vbh[g]);
                mma16816(oacc[2 * g + 1], plf, vbh[g] + 2);
            }
            #pragma unroll
            for (int g = 0; g < 4; g++) {
                mma16816(oacc[2 * g],     phf, vbl[g]);
                mma16816(oacc[2 * g + 1], phf, vbl[g] + 2);
            }
        }

        __syncthreads();
        if (c + 2 < SEQ / KT) load_kv((c + 2) * KT, c & 1);
    }

    float inv0 = 1.f / l0, inv1 = 1.f / l1;
    int row0 = q0 + w * 16 + grp;
    size_t ob0 = ((size_t)(b * SEQ) + row0) * INNER + h * 64;
    size_t ob1 = ob0 + 8 * INNER;
    #pragma unroll
    for (int ni = 0; ni < 8; ni++) {
        int col = ni * 8 + tig * 2;
        store_split2(oh + ob0 + col, ol + ob0 + col,
                     oacc[ni][0] * inv0, oacc[ni][1] * inv0);
        store_split2(oh + ob1 + col, ol + ob1 + col,
                     oacc[ni][2] * inv1, oacc[ni][3] * inv1);
    }
}

// ---------------------------------------------------------------------------
extern "C" void kernel_launch(void* const* d_in, const int* in_sizes, int n_in,
                              void* d_out, int out_size) {
    const float* x     = (const float*)d_in[0];
    const float* ln_g  = (const float*)d_in[1];
    const float* ln_b  = (const float*)d_in[2];
    const float* w_qkv = (const float*)d_in[3];
    const float* b_qkv = (const float*)d_in[4];
    const float* w_out = (const float*)d_in[5];
    const float* b_out = (const float*)d_in[6];
    float* out = (float*)d_out;

    __nv_bfloat16 *xnh, *xnl, *wqh, *wql, *woh, *wol, *ath, *atl;
    __nv_bfloat16 *qh, *ql, *kh, *kl, *vth, *vtl;
    float* qkvb;
    cudaGetSymbolAddress((void**)&xnh, g_xnh);
    cudaGetSymbolAddress((void**)&xnl, g_xnl);
    cudaGetSymbolAddress((void**)&wqh, g_wqh);
    cudaGetSymbolAddress((void**)&wql, g_wql);
    cudaGetSymbolAddress((void**)&woh, g_woh);
    cudaGetSymbolAddress((void**)&wol, g_wol);
    cudaGetSymbolAddress((void**)&ath, g_ath);
    cudaGetSymbolAddress((void**)&atl, g_atl);
    cudaGetSymbolAddress((void**)&qkvb, g_qkv);
    cudaGetSymbolAddress((void**)&qh,  g_qh);
    cudaGetSymbolAddress((void**)&ql,  g_ql);
    cudaGetSymbolAddress((void**)&kh,  g_kh);
    cudaGetSymbolAddress((void**)&kl,  g_kl);
    cudaGetSymbolAddress((void**)&vth, g_vth);
    cudaGetSymbolAddress((void**)&vtl, g_vtl);

    cudaFuncSetAttribute(gemm_mma, cudaFuncAttributeMaxDynamicSharedMemorySize,
                         GEMM_SMEM);
    cudaFuncSetAttribute(attn_mma, cudaFuncAttributeMaxDynamicSharedMemorySize,
                         ATTN_SMEM);

    ln_kernel<<<TOKENS, 256>>>(x, ln_g, ln_b, xnh, xnl);
    transpose_split<<<dim3(3 * INNER / 32, DIMX / 32), dim3(32, 8)>>>(
        w_qkv, wqh, wql, DIMX, 3 * INNER);
    transpose_split<<<dim3(DIMX / 32, INNER / 32), dim3(32, 8)>>>(
        w_out, woh, wol, INNER, DIMX);
    gemm_mma<<<dim3(3 * INNER / 128, TOKENS / 128), 256, GEMM_SMEM>>>(
        xnh, xnl, wqh, wql, b_qkv, qkvb, 3 * INNER);
    prep_qkv<<<dim3(SEQ / 64, HEADS, BATCH), 256>>>(
        qkvb, qh, ql, kh, kl, vth, vtl);
    attn_mma<<<dim3(SEQ / QT, HEADS, BATCH), 256, ATTN_SMEM>>>(
        qh, ql, kh, kl, vth, vtl, ath, atl);
    gemm_mma<<<dim3(DIMX / 128, TOKENS / 128), 256, GEMM_SMEM>>>(
        ath, atl, woh, wol, b_out, out, DIMX);
}

// round 15
// speedup vs baseline: 3.4351x; 1.1951x over previous
#include <cuda_runtime.h>
#include <cuda_bf16.h>
#include <cuda_fp16.h>
#include <cstdint>

#define DIMX 1024
#define TOKENS 8192
#define INNER 1024
#define HEADS 16
#define HEAD_DIM 64
#define SEQ 2048
#define BATCH 4
#define GK 1024
#define KCHUNK 32
#define NCHUNK (GK / KCHUNK)

// ---------------------------------------------------------------------------
// Scratch
// ---------------------------------------------------------------------------
__device__ __half         g_xh [TOKENS * DIMX];        // LN out, fp16 (A of QKV)
__device__ __half         g_wqh[3 * INNER * DIMX];     // w_qkv^T hi
__device__ __half         g_wql[3 * INNER * DIMX];     // w_qkv^T lo
__device__ __half         g_woh[DIMX * INNER];
__device__ __half         g_wol[DIMX * INNER];
__device__ float          g_qkv[TOKENS * 3 * INNER];   // fp32 QKV (attn input)
__device__ __half         g_ath[TOKENS * INNER];       // attention out, fp16
// head-major split QKV for attention (bf16 hi/lo, unchanged)
__device__ __nv_bfloat16 g_qh[BATCH * HEADS * SEQ * HEAD_DIM];
__device__ __nv_bfloat16 g_ql[BATCH * HEADS * SEQ * HEAD_DIM];
__device__ __nv_bfloat16 g_kh[BATCH * HEADS * SEQ * HEAD_DIM];
__device__ __nv_bfloat16 g_kl[BATCH * HEADS * SEQ * HEAD_DIM];
__device__ __nv_bfloat16 g_vth[BATCH * HEADS * HEAD_DIM * SEQ];  // [bh][d][s]
__device__ __nv_bfloat16 g_vtl[BATCH * HEADS * HEAD_DIM * SEQ];

// ---------------------------------------------------------------------------
// Helpers (base ISA only — target is bare sm_103)
// ---------------------------------------------------------------------------
__device__ __forceinline__ uint32_t smem_u32(const void* p) {
    uint32_t a;
    asm("{ .reg .u64 t; cvta.to.shared.u64 t, %1; cvt.u32.u64 %0, t; }" : "=r"(a) : "l"(p));
    return a;
}
#define CP_ASYNC16(dst, src) \
    asm volatile("cp.async.cg.shared.global [%0], [%1], 16;" :: "r"(dst), "l"(src) : "memory")
#define CP_COMMIT() asm volatile("cp.async.commit_group;" ::: "memory")
#define CP_WAIT(n)  asm volatile("cp.async.wait_group %0;" :: "n"(n) : "memory")

__device__ __forceinline__ void ldsm_x4(uint32_t* r, uint32_t addr) {
    asm volatile("ldmatrix.sync.aligned.m8n8.x4.shared.b16 {%0,%1,%2,%3}, [%4];"
                 : "=r"(r[0]), "=r"(r[1]), "=r"(r[2]), "=r"(r[3]) : "r"(addr));
}
// bf16 MMA (attention)
__device__ __forceinline__ void mma16816(float* c, const uint32_t* a, const uint32_t* b) {
    asm("mma.sync.aligned.m16n8k16.row.col.f32.bf16.bf16.f32 "
        "{%0,%1,%2,%3}, {%4,%5,%6,%7}, {%8,%9}, {%0,%1,%2,%3};"
        : "+f"(c[0]), "+f"(c[1]), "+f"(c[2]), "+f"(c[3])
        : "r"(a[0]), "r"(a[1]), "r"(a[2]), "r"(a[3]), "r"(b[0]), "r"(b[1]));
}
// fp16 MMA (GEMMs)
__device__ __forceinline__ void mma16816h(float* c, const uint32_t* a, const uint32_t* b) {
    asm("mma.sync.aligned.m16n8k16.row.col.f32.f16.f16.f32 "
        "{%0,%1,%2,%3}, {%4,%5,%6,%7}, {%8,%9}, {%0,%1,%2,%3};"
        : "+f"(c[0]), "+f"(c[1]), "+f"(c[2]), "+f"(c[3])
        : "r"(a[0]), "r"(a[1]), "r"(a[2]), "r"(a[3]), "r"(b[0]), "r"(b[1]));
}
__device__ __forceinline__ void split_bf(float v, __nv_bfloat16& h, __nv_bfloat16& l) {
    h = __float2bfloat16_rn(v);
    l = __float2bfloat16_rn(v - __bfloat162float(h));
}
__device__ __forceinline__ void split_pack(float a, float b, uint32_t& hi, uint32_t& lo) {
    __nv_bfloat16 ha = __float2bfloat16_rn(a), hb = __float2bfloat16_rn(b);
    __nv_bfloat162 hp = __halves2bfloat162(ha, hb);
    hi = *reinterpret_cast<uint32_t*>(&hp);
    __nv_bfloat162 lp = __halves2bfloat162(
        __float2bfloat16_rn(a - __bfloat162float(ha)),
        __float2bfloat16_rn(b - __bfloat162float(hb)));
    lo = *reinterpret_cast<uint32_t*>(&lp);
}
__device__ __forceinline__ void store_split2(__nv_bfloat16* ph, __nv_bfloat16* pl,
                                             float a, float b) {
    __nv_bfloat16 ha, la, hb, lb;
    split_bf(a, ha, la); split_bf(b, hb, lb);
    *reinterpret_cast<__nv_bfloat162*>(ph) = __halves2bfloat162(ha, hb);
    *reinterpret_cast<__nv_bfloat162*>(pl) = __halves2bfloat162(la, lb);
}

// ---------------------------------------------------------------------------
// LayerNorm -> fp16 (single component)
// ---------------------------------------------------------------------------
__global__ void __launch_bounds__(256) ln_kernel(const float* __restrict__ x,
                                                 const float* __restrict__ g,
                                                 const float* __restrict__ b,
                                                 __half* __restrict__ oh) {
    int row = blockIdx.x;
    int t = threadIdx.x;
    float4 v = reinterpret_cast<const float4*>(x + (size_t)row * DIMX)[t];
    float s = v.x + v.y + v.z + v.w;
    float s2 = v.x * v.x + v.y * v.y + v.z * v.z + v.w * v.w;
    #pragma unroll
    for (int o = 16; o; o >>= 1) {
        s  += __shfl_xor_sync(0xffffffffu, s,  o);
        s2 += __shfl_xor_sync(0xffffffffu, s2, o);
    }
    __shared__ float ws[8], ws2[8];
    int w = t >> 5, l = t & 31;
    if (l == 0) { ws[w] = s; ws2[w] = s2; }
    __syncthreads();
    float sum = 0.f, sum2 = 0.f;
    #pragma unroll
    for (int i = 0; i < 8; i++) { sum += ws[i]; sum2 += ws2[i]; }
    float mu = sum * (1.0f / DIMX);
    float var = sum2 * (1.0f / DIMX) - mu * mu;
    float rstd = rsqrtf(var + 1e-5f);

    float4 gv = reinterpret_cast<const float4*>(g)[t];
    float4 bv = reinterpret_cast<const float4*>(b)[t];
    float o0 = (v.x - mu) * rstd * gv.x + bv.x;
    float o1 = (v.y - mu) * rstd * gv.y + bv.y;
    float o2 = (v.z - mu) * rstd * gv.z + bv.z;
    float o3 = (v.w - mu) * rstd * gv.w + bv.w;
    size_t p = (size_t)row * DIMX + t * 4;
    __half2* ph = reinterpret_cast<__half2*>(oh + p);
    ph[0] = __floats2half2_rn(o0, o1);
    ph[1] = __floats2half2_rn(o2, o3);
}

// ---------------------------------------------------------------------------
// Weight transpose + split: W[K][N] fp32 -> T{hi,lo}[N][K] fp16
// ---------------------------------------------------------------------------
__global__ void __launch_bounds__(256) transpose_split(const float* __restrict__ W,
                                                       __half* __restrict__ Th,
                                                       __half* __restrict__ Tl,
                                                       int K, int N) {
    __shared__ float tile[32][33];
    int n0 = blockIdx.x * 32, k0 = blockIdx.y * 32;
    int tx = threadIdx.x, ty = threadIdx.y;
    #pragma unroll
    for (int j = 0; j < 4; j++)
        tile[ty + j * 8][tx] = W[(size_t)(k0 + ty + j * 8) * N + n0 + tx];
    __syncthreads();
    #pragma unroll
    for (int j = 0; j < 4; j++) {
        float v = tile[tx][ty + j * 8];
        __half h = __float2half_rn(v);
        __half l = __float2half_rn(v - __half2float(h));
        size_t p = (size_t)(n0 + ty + j * 8) * K + k0 + tx;
        Th[p] = h; Tl[p] = l;
    }
}

// ---------------------------------------------------------------------------
// fp16 GEMM, 2 MMAs/product: C = A_fp16 @ (B_hi + B_lo)^T + bias
// CTA 128x128, 8 warps (2x4), BK=32, 3-stage cp.async, 2 CTAs/SM.
// ---------------------------------------------------------------------------
#define ROWB 80
#define COMP_BYTES (128 * ROWB)        // 10240
#define STAGE_BYTES (3 * COMP_BYTES)   // A, Bh, Bl = 30720
#define GEMM_SMEM (3 * STAGE_BYTES)    // 92160

__global__ void __launch_bounds__(256, 2) gemm_mma(const __half* __restrict__ A,
                                                   const __half* __restrict__ Bhi,
                                                   const __half* __restrict__ Blo,
                                                   const float* __restrict__ bias,
                                                   float* __restrict__ C, int Ntot) {
    extern __shared__ char smem[];
    const uint32_t sbase = smem_u32(smem);

    int tid = threadIdx.x;
    int wid = tid >> 5, lane = tid & 31;
    int wm = wid >> 2, wn = wid & 3;
    int grp = lane >> 2, tig = lane & 3;
    const int lrow = lane & 15;
    const int lc16 = (lane >> 4) * 16;

    const int m0 = blockIdx.y * 128;
    const int n0 = blockIdx.x * 128;

    const __half* gA = A + (size_t)m0 * GK;
    const __half* gB[2] = { Bhi + (size_t)n0 * GK, Blo + (size_t)n0 * GK };

    auto load_chunk = [&](int c, int st) {
        uint32_t sa = sbase + st * STAGE_BYTES;
        #pragma unroll
        for (int i = 0; i < 2; i++) {
            int id = tid + i * 256;
            int r = id >> 2;
            int q = id & 3;
            uint32_t dst = sa + (uint32_t)(r * ROWB + q * 16);
            size_t gsrc = (size_t)r * GK + c * KCHUNK + q * 8;
            CP_ASYNC16(dst + 0 * COMP_BYTES, gA + gsrc);
            CP_ASYNC16(dst + 1 * COMP_BYTES, gB[0] + gsrc);
            CP_ASYNC16(dst + 2 * COMP_BYTES, gB[1] + gsrc);
        }
        CP_COMMIT();
    };

    load_chunk(0, 0);
    load_chunk(1, 1);
    load_chunk(2, 2);

    float acc[4][4][4];
    #pragma unroll
    for (int mi = 0; mi < 4; mi++)
        #pragma unroll
        for (int ni = 0; ni < 4; ni++)
            #pragma unroll
            for (int j = 0; j < 4; j++) acc[mi][ni][j] = 0.f;

    const uint32_t aOff = (uint32_t)(wm * 64 + lrow) * ROWB + lc16;
    const uint32_t bOff = (uint32_t)(wn * 32 + lrow) * ROWB + lc16;

    for (int c = 0; c < NCHUNK; c++) {
        if (c < NCHUNK - 2)       CP_WAIT(2);
        else if (c == NCHUNK - 2) CP_WAIT(1);
        else                      CP_WAIT(0);
        __syncthreads();

        uint32_t sa = sbase + (c % 3) * STAGE_BYTES;
        uint32_t sA = sa, sBh = sa + COMP_BYTES, sBl = sa + 2 * COMP_BYTES;

        #pragma unroll
        for (int s = 0; s < 2; s++) {
            const uint32_t ko = (uint32_t)s * 32;
            uint32_t bh[2][4], bl[2][4];
            #pragma unroll
            for (int np = 0; np < 2; np++) {
                uint32_t ba = bOff + (uint32_t)np * 16 * ROWB + ko;
                ldsm_x4(bh[np], sBh + ba);
                ldsm_x4(bl[np], sBl + ba);
            }
            #pragma unroll
            for (int mi = 0; mi < 4; mi++) {
                uint32_t ah[4];
                ldsm_x4(ah, sA + aOff + (uint32_t)mi * 16 * ROWB + ko);
                #pragma unroll
                for (int ni = 0; ni < 4; ni++) {
                    uint32_t bf[2] = { bh[ni >> 1][ni & 1], bh[ni >> 1][2 + (ni & 1)] };
                    mma16816h(acc[mi][ni], ah, bf);
                }
                #pragma unroll
                for (int ni = 0; ni < 4; ni++) {
                    uint32_t bf[2] = { bl[ni >> 1][ni & 1], bl[ni >> 1][2 + (ni & 1)] };
                    mma16816h(acc[mi][ni], ah, bf);
                }
            }
        }
        __syncthreads();
        if (c + 3 < NCHUNK) load_chunk(c + 3, c % 3);
    }

    #pragma unroll
    for (int mi = 0; mi < 4; mi++) {
        int row0 = m0 + wm * 64 + mi * 16 + grp;
        #pragma unroll
        for (int ni = 0; ni < 4; ni++) {
            int col = n0 + wn * 32 + ni * 8 + tig * 2;
            float bx = bias[col], by = bias[col + 1];
            float2* p0 = reinterpret_cast<float2*>(C + (size_t)row0 * Ntot + col);
            float2* p1 = reinterpret_cast<float2*>(C + (size_t)(row0 + 8) * Ntot + col);
            *p0 = make_float2(acc[mi][ni][0] + bx, acc[mi][ni][1] + by);
            *p1 = make_float2(acc[mi][ni][2] + bx, acc[mi][ni][3] + by);
        }
    }
}

// ---------------------------------------------------------------------------
// Prepass: fp32 QKV -> head-major bf16 hi/lo; Q pre-scaled; V transposed
// ---------------------------------------------------------------------------
__global__ void __launch_bounds__(256) prep_qkv(const float* __restrict__ qkv,
                                                __nv_bfloat16* __restrict__ qh,
                                                __nv_bfloat16* __restrict__ ql,
                                                __nv_bfloat16* __restrict__ kh,
                                                __nv_bfloat16* __restrict__ kl,
                                                __nv_bfloat16* __restrict__ vth,
                                                __nv_bfloat16* __restrict__ vtl) {
    __shared__ float vs[64][65];
    int st = blockIdx.x, h = blockIdx.y, b = blockIdx.z;
    int bh = b * HEADS + h;
    int s0 = st * 64;
    int tid = threadIdx.x;

    #pragma unroll
    for (int i = 0; i < 4; i++) {
        int id = tid + i * 256;
        int row = id >> 4, c4 = (id & 15) * 4;
        const float* src = qkv + (size_t)(b * SEQ + s0 + row) * 3072 + h * 64 + c4;
        size_t dst = ((size_t)bh * SEQ + s0 + row) * 64 + c4;
        float4 qv = *reinterpret_cast<const float4*>(src);
        store_split2(qh + dst,     ql + dst,     qv.x * 0.125f, qv.y * 0.125f);
        store_split2(qh + dst + 2, ql + dst + 2, qv.z * 0.125f, qv.w * 0.125f);
        float4 kv = *reinterpret_cast<const float4*>(src + 1024);
        store_split2(kh + dst,     kl + dst,     kv.x, kv.y);
        store_split2(kh + dst + 2, kl + dst + 2, kv.z, kv.w);
        float4 vv = *reinterpret_cast<const float4*>(src + 2048);
        vs[row][c4 + 0] = vv.x; vs[row][c4 + 1] = vv.y;
        vs[row][c4 + 2] = vv.z; vs[row][c4 + 3] = vv.w;
    }
    __syncthreads();
    #pragma unroll
    for (int i = 0; i < 4; i++) {
        int id = tid + i * 256;
        int d = id >> 4, s4 = (id & 15) * 4;
        size_t dst = ((size_t)bh * HEAD_DIM + d) * SEQ + s0 + s4;
        store_split2(vth + dst,     vtl + dst,     vs[s4][d],     vs[s4 + 1][d]);
        store_split2(vth + dst + 2, vtl + dst + 2, vs[s4 + 2][d], vs[s4 + 3][d]);
    }
}

// ---------------------------------------------------------------------------
// Flash attention via mma.sync (bf16x3) — unchanged math; fp16 single output
// ---------------------------------------------------------------------------
#define QT 128
#define KT 64
#define RSTR 144
#define SM_QBYTES (QT * RSTR)
#define SM_STAGE0 (2 * SM_QBYTES)
#define TILE_B (KT * RSTR)
#define STAGE_B (4 * TILE_B)
#define ATTN_SMEM (SM_STAGE0 + 2 * STAGE_B)

__global__ void __launch_bounds__(256, 1)
attn_mma(const __nv_bfloat16* __restrict__ qh, const __nv_bfloat16* __restrict__ ql,
         const __nv_bfloat16* __restrict__ kh, const __nv_bfloat16* __restrict__ kl,
         const __nv_bfloat16* __restrict__ vth, const __nv_bfloat16* __restrict__ vtl,
         __half* __restrict__ oh) {
    extern __shared__ char smem[];
    const uint32_t sb = smem_u32(smem);
    const int tid = threadIdx.x;
    const int w = tid >> 5, lane = tid & 31;
    const int grp = lane >> 2, tig = lane & 3;
    const int qt = blockIdx.x, h = blockIdx.y, b = blockIdx.z;
    const int bh = b * HEADS + h;
    const int q0 = qt * QT;

    const __nv_bfloat16* qsrc[2] = { qh + ((size_t)bh * SEQ + q0) * 64,
                                     ql + ((size_t)bh * SEQ + q0) * 64 };
    const __nv_bfloat16* ksrc[2] = { kh + (size_t)bh * SEQ * 64,
                                     kl + (size_t)bh * SEQ * 64 };
    const __nv_bfloat16* vsrc[2] = { vth + (size_t)bh * HEAD_DIM * SEQ,
                                     vtl + (size_t)bh * HEAD_DIM * SEQ };

    #pragma unroll
    for (int i = 0; i < 8; i++) {
        int id = tid + i * 256;
        int comp = id >> 10, rem = id & 1023;
        int row = rem >> 3, qq = rem & 7;
        CP_ASYNC16(sb + comp * SM_QBYTES + row * RSTR + qq * 16,
                   qsrc[comp] + (size_t)row * 64 + qq * 8);
    }
    CP_COMMIT();

    auto load_kv = [&](int kt_, int stg) {
        uint32_t sa = sb + SM_STAGE0 + stg * STAGE_B;
        #pragma unroll
        for (int i = 0; i < 8; i++) {
            int id = tid + i * 256;
            int arr = id >> 9, rem = id & 511;
            int row = rem >> 3, qq = rem & 7;
            uint32_t dst = sa + arr * TILE_B + row * RSTR + qq * 16;
            const __nv_bfloat16* src;
            if (arr == 0)      src = ksrc[0] + (size_t)(kt_ + row) * 64 + qq * 8;
            else if (arr == 1) src = ksrc[1] + (size_t)(kt_ + row) * 64 + qq * 8;
            else if (arr == 2) src = vsrc[0] + (size_t)row * SEQ + kt_ + qq * 8;
            else               src = vsrc[1] + (size_t)row * SEQ + kt_ + qq * 8;
            CP_ASYNC16(dst, src);
        }
        CP_COMMIT();
    };

    load_kv(0, 0);
    load_kv(KT, 1);

    CP_WAIT(2);
    __syncthreads();

    uint32_t qfh[4][4], qfl[4][4];
    {
        int arow = w * 16 + ((lane >> 3) & 1) * 8 + (lane & 7);
        int acol = (lane >> 4) * 16;
        #pragma unroll
        for (int j = 0; j < 4; j++) {
            ldsm_x4(qfh[j], sb + arow * RSTR + j * 32 + acol);
            ldsm_x4(qfl[j], sb + SM_QBYTES + arow * RSTR + j * 32 + acol);
        }
    }

    float m0 = -1e30f, m1 = -1e30f, l0 = 0.f, l1 = 0.f;
    float oacc[8][4];
    #pragma unroll
    for (int ni = 0; ni < 8; ni++)
        #pragma unroll
        for (int j = 0; j < 4; j++) oacc[ni][j] = 0.f;

    const int brow = (lane >> 4) * 8 + (lane & 7);
    const int bcol = ((lane >> 3) & 1) * 16;

    for (int c = 0; c < SEQ / KT; c++) {
        if (c < SEQ / KT - 1) CP_WAIT(1); else CP_WAIT(0);
        __syncthreads();
        uint32_t sa = sb + SM_STAGE0 + (c & 1) * STAGE_B;
        uint32_t sKh = sa, sKl = sa + TILE_B;
        uint32_t sVh = sa + 2 * TILE_B, sVl = sa + 3 * TILE_B;

        float sacc[8][4];
        #pragma unroll
        for (int ni = 0; ni < 8; ni++)
            #pragma unroll
            for (int j = 0; j < 4; j++) sacc[ni][j] = 0.f;

        #pragma unroll
        for (int j = 0; j < 4; j++) {
            uint32_t kbh[4][4], kbl[4][4];
            #pragma unroll
            for (int g = 0; g < 4; g++) {
                uint32_t ba = (uint32_t)(g * 16 + brow) * RSTR + j * 32 + bcol;
                ldsm_x4(kbh[g], sKh + ba);
                ldsm_x4(kbl[g], sKl + ba);
            }
            #pragma unroll
            for (int g = 0; g < 4; g++) {
                mma16816(sacc[2 * g],     qfh[j], kbh[g]);
                mma16816(sacc[2 * g + 1], qfh[j], kbh[g] + 2);
            }
            #pragma unroll
            for (int g = 0; g < 4; g++) {
                mma16816(sacc[2 * g],     qfl[j], kbh[g]);
                mma16816(sacc[2 * g + 1], qfl[j], kbh[g] + 2);
            }
            #pragma unroll
            for (int g = 0; g < 4; g++) {
                mma16816(sacc[2 * g],     qfh[j], kbl[g]);
                mma16816(sacc[2 * g + 1], qfh[j], kbl[g] + 2);
            }
        }

        float mx0 = -1e30f, mx1 = -1e30f;
        #pragma unroll
        for (int ni = 0; ni < 8; ni++) {
            mx0 = fmaxf(mx0, fmaxf(sacc[ni][0], sacc[ni][1]));
            mx1 = fmaxf(mx1, fmaxf(sacc[ni][2], sacc[ni][3]));
        }
        mx0 = fmaxf(mx0, __shfl_xor_sync(0xffffffffu, mx0, 1));
        mx0 = fmaxf(mx0, __shfl_xor_sync(0xffffffffu, mx0, 2));
        mx1 = fmaxf(mx1, __shfl_xor_sync(0xffffffffu, mx1, 1));
        mx1 = fmaxf(mx1, __shfl_xor_sync(0xffffffffu, mx1, 2));
        float mn0 = fmaxf(m0, mx0), mn1 = fmaxf(m1, mx1);
        float al0 = __expf(m0 - mn0), al1 = __expf(m1 - mn1);
        m0 = mn0; m1 = mn1;
        float rs0 = 0.f, rs1 = 0.f;
        #pragma unroll
        for (int ni = 0; ni < 8; ni++) {
            sacc[ni][0] = __expf(sacc[ni][0] - mn0);
            sacc[ni][1] = __expf(sacc[ni][1] - mn0);
            sacc[ni][2] = __expf(sacc[ni][2] - mn1);
            sacc[ni][3] = __expf(sacc[ni][3] - mn1);
            rs0 += sacc[ni][0] + sacc[ni][1];
            rs1 += sacc[ni][2] + sacc[ni][3];
        }
        rs0 += __shfl_xor_sync(0xffffffffu, rs0, 1);
        rs0 += __shfl_xor_sync(0xffffffffu, rs0, 2);
        rs1 += __shfl_xor_sync(0xffffffffu, rs1, 1);
        rs1 += __shfl_xor_sync(0xffffffffu, rs1, 2);
        l0 = l0 * al0 + rs0;
        l1 = l1 * al1 + rs1;

        #pragma unroll
        for (int ni = 0; ni < 8; ni++) {
            oacc[ni][0] *= al0; oacc[ni][1] *= al0;
            oacc[ni][2] *= al1; oacc[ni][3] *= al1;
        }

        #pragma unroll
        for (int j = 0; j < 4; j++) {
            uint32_t phf[4], plf[4];
            split_pack(sacc[2 * j][0],     sacc[2 * j][1],     phf[0], plf[0]);
            split_pack(sacc[2 * j][2],     sacc[2 * j][3],     phf[1], plf[1]);
            split_pack(sacc[2 * j + 1][0], sacc[2 * j + 1][1], phf[2], plf[2]);
            split_pack(sacc[2 * j + 1][2], sacc[2 * j + 1][3], phf[3], plf[3]);
            uint32_t vbh[4][4], vbl[4][4];
            #pragma unroll
            for (int g = 0; g < 4; g++) {
                uint32_t ba = (uint32_t)(g * 16 + brow) * RSTR + j * 32 + bcol;
                ldsm_x4(vbh[g], sVh + ba);
                ldsm_x4(vbl[g], sVl + ba);
            }
            #pragma unroll
            for (int g = 0; g < 4; g++) {
                mma16816(oacc[2 * g],     phf, vbh[g]);
                mma16816(oacc[2 * g + 1], phf, vbh[g] + 2);
            }
            #pragma unroll
            for (int g = 0; g < 4; g++) {
                mma16816(oacc[2 * g],     plf, vbh[g]);
                mma16816(oacc[2 * g + 1], plf, vbh[g] + 2);
            }
            #pragma unroll
            for (int g = 0; g < 4; g++) {
                mma16816(oacc[2 * g],     phf, vbl[g]);
                mma16816(oacc[2 * g + 1], phf, vbl[g] + 2);
            }
        }

        __syncthreads();
        if (c + 2 < SEQ / KT) load_kv((c + 2) * KT, c & 1);
    }

    float inv0 = 1.f / l0, inv1 = 1.f / l1;
    int row0 = q0 + w * 16 + grp;
    size_t ob0 = ((size_t)(b * SEQ) + row0) * INNER + h * 64;
    size_t ob1 = ob0 + 8 * INNER;
    #pragma unroll
    for (int ni = 0; ni < 8; ni++) {
        int col = ni * 8 + tig * 2;
        *reinterpret_cast<__half2*>(oh + ob0 + col) =
            __floats2half2_rn(oacc[ni][0] * inv0, oacc[ni][1] * inv0);
        *reinterpret_cast<__half2*>(oh + ob1 + col) =
            __floats2half2_rn(oacc[ni][2] * inv1, oacc[ni][3] * inv1);
    }
}

// ---------------------------------------------------------------------------
extern "C" void kernel_launch(void* const* d_in, const int* in_sizes, int n_in,
                              void* d_out, int out_size) {
    const float* x     = (const float*)d_in[0];
    const float* ln_g  = (const float*)d_in[1];
    const float* ln_b  = (const float*)d_in[2];
    const float* w_qkv = (const float*)d_in[3];
    const float* b_qkv = (const float*)d_in[4];
    const float* w_out = (const float*)d_in[5];
    const float* b_out = (const float*)d_in[6];
    float* out = (float*)d_out;

    __half *xh, *wqh, *wql, *woh, *wol, *ath;
    __nv_bfloat16 *qh, *ql, *kh, *kl, *vth, *vtl;
    float* qkvb;
    cudaGetSymbolAddress((void**)&xh,  g_xh);
    cudaGetSymbolAddress((void**)&wqh, g_wqh);
    cudaGetSymbolAddress((void**)&wql, g_wql);
    cudaGetSymbolAddress((void**)&woh, g_woh);
    cudaGetSymbolAddress((void**)&wol, g_wol);
    cudaGetSymbolAddress((void**)&ath, g_ath);
    cudaGetSymbolAddress((void**)&qkvb, g_qkv);
    cudaGetSymbolAddress((void**)&qh,  g_qh);
    cudaGetSymbolAddress((void**)&ql,  g_ql);
    cudaGetSymbolAddress((void**)&kh,  g_kh);
    cudaGetSymbolAddress((void**)&kl,  g_kl);
    cudaGetSymbolAddress((void**)&vth, g_vth);
    cudaGetSymbolAddress((void**)&vtl, g_vtl);

    cudaFuncSetAttribute(gemm_mma, cudaFuncAttributeMaxDynamicSharedMemorySize,
                         GEMM_SMEM);
    cudaFuncSetAttribute(attn_mma, cudaFuncAttributeMaxDynamicSharedMemorySize,
                         ATTN_SMEM);

    ln_kernel<<<TOKENS, 256>>>(x, ln_g, ln_b, xh);
    transpose_split<<<dim3(3 * INNER / 32, DIMX / 32), dim3(32, 8)>>>(
        w_qkv, wqh, wql, DIMX, 3 * INNER);
    transpose_split<<<dim3(DIMX / 32, INNER / 32), dim3(32, 8)>>>(
        w_out, woh, wol, INNER, DIMX);
    gemm_mma<<<dim3(3 * INNER / 128, TOKENS / 128), 256, GEMM_SMEM>>>(
        xh, wqh, wql, b_qkv, qkvb, 3 * INNER);
    prep_qkv<<<dim3(SEQ / 64, HEADS, BATCH), 256>>>(
        qkvb, qh, ql, kh, kl, vth, vtl);
    attn_mma<<<dim3(SEQ / QT, HEADS, BATCH), 256, ATTN_SMEM>>>(
        qh, ql, kh, kl, vth, vtl, ath);
    gemm_mma<<<dim3(DIMX / 128, TOKENS / 128), 256, GEMM_SMEM>>>(
        ath, woh, wol, b_out, out, DIMX);
}